// round 10
// baseline (speedup 1.0000x reference)
#include <cuda_runtime.h>
#include <math.h>

#define BB 2
#define SS 2048
#define DD 512
#define HH 8
#define DK 64
#define M_TOTAL (BB*SS)   // 4096

// Scratch (allocation-free)
__device__ float g_Q[BB*HH*SS*DK];
__device__ float g_K[BB*HH*SS*DK];
__device__ float g_V[BB*HH*SS*DK];
__device__ float g_attn[BB*SS*DD];

// ---------------------------------------------------------------------------
__device__ __forceinline__ unsigned f2t(float x) {
    unsigned r;
    asm("cvt.rna.tf32.f32 %0, %1;" : "=r"(r) : "f"(x));
    return r;
}

__device__ __forceinline__ void mma8(float* c,
                                     unsigned a0, unsigned a1, unsigned a2, unsigned a3,
                                     unsigned b0, unsigned b1) {
    asm volatile(
        "mma.sync.aligned.m16n8k8.row.col.f32.tf32.tf32.f32 "
        "{%0,%1,%2,%3}, {%4,%5,%6,%7}, {%8,%9}, {%0,%1,%2,%3};"
        : "+f"(c[0]), "+f"(c[1]), "+f"(c[2]), "+f"(c[3])
        : "r"(a0), "r"(a1), "r"(a2), "r"(a3), "r"(b0), "r"(b1));
}

#define CP_ASYNC16(smem_u32, gptr) \
    asm volatile("cp.async.cg.shared.global [%0], [%1], 16;" :: "r"(smem_u32), "l"(gptr))
#define CP_COMMIT()  asm volatile("cp.async.commit_group;" ::: "memory")
#define CP_WAIT0()   asm volatile("cp.async.wait_group 0;" ::: "memory")

// ---------------------------------------------------------------------------
// 3xTF32 GEMM with register-prefetch double buffering (unchanged from R7).
// C = (A @ W^T + bias) * alpha. Block 128x64, BK=32, 8 warps (4x2), pitch 36.
// MODE 0: row-major [M,N].  MODE 1: head-split [B,H,S,DK] + tf32-RNA rounding.
// ---------------------------------------------------------------------------
template<int MODE>
__global__ __launch_bounds__(256)
void proj_kernel(const float* __restrict__ A, const float* __restrict__ W,
                 const float* __restrict__ bias, float* __restrict__ C,
                 float alpha) {
    extern __shared__ unsigned sh[];
    unsigned (*Ab)[36] = (unsigned(*)[36])sh;                       // 128x36
    unsigned (*Al)[36] = (unsigned(*)[36])(sh + 128*36);            // 128x36
    unsigned (*Bb)[36] = (unsigned(*)[36])(sh + 2*128*36);          // 64x36
    unsigned (*Bl)[36] = (unsigned(*)[36])(sh + 2*128*36 + 64*36);  // 64x36

    const int tid  = threadIdx.x;
    const int lane = tid & 31;
    const int warp = tid >> 5;
    const int g = lane >> 2, c = lane & 3;
    const int wm = warp & 3, wn = warp >> 2;
    const int m0 = blockIdx.y * 128, n0 = blockIdx.x * 64;

    int ar[4], ac[4], wrr[2], wcc[2];
    #pragma unroll
    for (int i = 0; i < 4; i++) {
        const int f = tid + i * 256;
        ar[i] = f >> 3; ac[i] = (f & 7) * 4;
    }
    #pragma unroll
    for (int i = 0; i < 2; i++) {
        const int f = tid + i * 256;
        wrr[i] = f >> 3; wcc[i] = (f & 7) * 4;
    }

    float4 ra[4], rw[2];
    #pragma unroll
    for (int i = 0; i < 4; i++)
        ra[i] = *(const float4*)(A + (size_t)(m0 + ar[i]) * 512 + ac[i]);
    #pragma unroll
    for (int i = 0; i < 2; i++)
        rw[i] = *(const float4*)(W + (size_t)(n0 + wrr[i]) * 512 + wcc[i]);

    float acc[2][4][4] = {};

    for (int kt = 0; kt < 512; kt += 32) {
        __syncthreads();
        #pragma unroll
        for (int i = 0; i < 4; i++) {
            float vv[4] = {ra[i].x, ra[i].y, ra[i].z, ra[i].w};
            unsigned hb[4], lb[4];
            #pragma unroll
            for (int j = 0; j < 4; j++) {
                hb[j] = f2t(vv[j]);
                lb[j] = f2t(vv[j] - __uint_as_float(hb[j]));
            }
            *(uint2*)&Ab[ar[i]][ac[i]]     = make_uint2(hb[0], hb[1]);
            *(uint2*)&Ab[ar[i]][ac[i] + 2] = make_uint2(hb[2], hb[3]);
            *(uint2*)&Al[ar[i]][ac[i]]     = make_uint2(lb[0], lb[1]);
            *(uint2*)&Al[ar[i]][ac[i] + 2] = make_uint2(lb[2], lb[3]);
        }
        #pragma unroll
        for (int i = 0; i < 2; i++) {
            float vv[4] = {rw[i].x, rw[i].y, rw[i].z, rw[i].w};
            unsigned hb[4], lb[4];
            #pragma unroll
            for (int j = 0; j < 4; j++) {
                hb[j] = f2t(vv[j]);
                lb[j] = f2t(vv[j] - __uint_as_float(hb[j]));
            }
            *(uint2*)&Bb[wrr[i]][wcc[i]]     = make_uint2(hb[0], hb[1]);
            *(uint2*)&Bb[wrr[i]][wcc[i] + 2] = make_uint2(hb[2], hb[3]);
            *(uint2*)&Bl[wrr[i]][wcc[i]]     = make_uint2(lb[0], lb[1]);
            *(uint2*)&Bl[wrr[i]][wcc[i] + 2] = make_uint2(lb[2], lb[3]);
        }
        __syncthreads();

        if (kt + 32 < 512) {
            #pragma unroll
            for (int i = 0; i < 4; i++)
                ra[i] = *(const float4*)(A + (size_t)(m0 + ar[i]) * 512 + kt + 32 + ac[i]);
            #pragma unroll
            for (int i = 0; i < 2; i++)
                rw[i] = *(const float4*)(W + (size_t)(n0 + wrr[i]) * 512 + kt + 32 + wcc[i]);
        }

        #pragma unroll
        for (int d = 0; d < 4; d++) {
            const int k8 = d * 8;
            unsigned ab[2][4], al[2][4], bb[4][2], bl[4][2];
            #pragma unroll
            for (int mi = 0; mi < 2; mi++) {
                const int rb = wm * 32 + mi * 16;
                ab[mi][0] = Ab[rb + g][k8 + c];     ab[mi][1] = Ab[rb + g + 8][k8 + c];
                ab[mi][2] = Ab[rb + g][k8 + c + 4]; ab[mi][3] = Ab[rb + g + 8][k8 + c + 4];
                al[mi][0] = Al[rb + g][k8 + c];     al[mi][1] = Al[rb + g + 8][k8 + c];
                al[mi][2] = Al[rb + g][k8 + c + 4]; al[mi][3] = Al[rb + g + 8][k8 + c + 4];
            }
            #pragma unroll
            for (int ni = 0; ni < 4; ni++) {
                const int cb = wn * 32 + ni * 8;
                bb[ni][0] = Bb[cb + g][k8 + c];  bb[ni][1] = Bb[cb + g][k8 + c + 4];
                bl[ni][0] = Bl[cb + g][k8 + c];  bl[ni][1] = Bl[cb + g][k8 + c + 4];
            }
            #pragma unroll
            for (int mi = 0; mi < 2; mi++)
                #pragma unroll
                for (int ni = 0; ni < 4; ni++) {
                    mma8(acc[mi][ni], ab[mi][0], ab[mi][1], ab[mi][2], ab[mi][3], bb[ni][0], bb[ni][1]);
                    mma8(acc[mi][ni], ab[mi][0], ab[mi][1], ab[mi][2], ab[mi][3], bl[ni][0], bl[ni][1]);
                    mma8(acc[mi][ni], al[mi][0], al[mi][1], al[mi][2], al[mi][3], bb[ni][0], bb[ni][1]);
                }
        }
    }

    #pragma unroll
    for (int mi = 0; mi < 2; mi++) {
        const int r0 = m0 + wm * 32 + mi * 16 + g;
        #pragma unroll
        for (int ni = 0; ni < 4; ni++) {
            const int cc = n0 + wn * 32 + ni * 8 + c * 2;
            const float b0 = bias[cc], b1 = bias[cc + 1];
            float v[4];
            v[0] = (acc[mi][ni][0] + b0) * alpha;
            v[1] = (acc[mi][ni][1] + b1) * alpha;
            v[2] = (acc[mi][ni][2] + b0) * alpha;
            v[3] = (acc[mi][ni][3] + b1) * alpha;
            #pragma unroll
            for (int p = 0; p < 2; p++) {
                const int m = r0 + p * 8;
                #pragma unroll
                for (int q = 0; q < 2; q++) {
                    const int n = cc + q;
                    float val = v[p * 2 + q];
                    if (MODE == 0) {
                        C[(size_t)m * 512 + n] = val;
                    } else {
                        val = __uint_as_float(f2t(val));   // pre-round for attn cp.async
                        const int b_ = m >> 11, s_ = m & 2047;
                        const int h_ = n >> 6, dk = n & 63;
                        C[(((size_t)(b_ * HH + h_)) * SS + s_) * DK + dk] = val;
                    }
                }
            }
        }
    }
}

// ---------------------------------------------------------------------------
// Flash attention: 256 threads, 8 warps, 32 q-rows per warp (2 m-subtiles of
// 16, processed sequentially through QK+softmax to cap register pressure).
// K/V crossbar bytes amortize over 2x the MMAs vs R7. cp.async double-buffered
// K/V, exp2 softmax.
// smem (words): Qs[256][68] @0 | Ks[2][64][68] @17408 | Vs[2][64][72] @26112
//               | Ps[256][68] @35328  -> 52736 words = 210944 B
// ---------------------------------------------------------------------------
#define QS_OFF 0
#define KS_OFF 17408
#define VS_OFF 26112
#define PS_OFF 35328

__global__ __launch_bounds__(256)
void attn_kernel(const float* __restrict__ Q, const float* __restrict__ K,
                 const float* __restrict__ V, float* __restrict__ Out) {
    extern __shared__ unsigned sh[];
    unsigned (*Qs)[68] = (unsigned(*)[68])(sh + QS_OFF);
    unsigned (*Ps)[68] = (unsigned(*)[68])(sh + PS_OFF);

    const int tid  = threadIdx.x;
    const int lane = tid & 31;
    const int warp = tid >> 5;       // 0..7
    const int g = lane >> 2, c = lane & 3;
    const int wr32 = warp * 32;      // 0..224
    const int qt = blockIdx.x;       // 0..7
    const int bh = blockIdx.y;       // 0..15

    const float* Qb = Q + (size_t)bh * SS * DK + (size_t)qt * 256 * DK;
    const float* Kb = K + (size_t)bh * SS * DK;
    const float* Vb = V + (size_t)bh * SS * DK;

    const unsigned sbase = (unsigned)__cvta_generic_to_shared(sh);

    // K/V tile load coords: 64x64 floats = 1024 16B-chunks, 4 per thread
    int rr[4], cc4[4];
    #pragma unroll
    for (int i = 0; i < 4; i++) {
        const int f = tid + i * 256;
        rr[i] = f >> 4;
        cc4[i] = (f & 15) * 4;
    }

    // prologue: stage 0 K/V
    #pragma unroll
    for (int i = 0; i < 4; i++) {
        CP_ASYNC16(sbase + (KS_OFF + rr[i]*68 + cc4[i]) * 4, Kb + rr[i]*64 + cc4[i]);
        CP_ASYNC16(sbase + (VS_OFF + rr[i]*72 + cc4[i]) * 4, Vb + rr[i]*64 + cc4[i]);
    }
    CP_COMMIT();

    // Q tile -> tf32 smem (256x64)
    #pragma unroll
    for (int i = 0; i < 16; i++) {
        const int f = tid + i * 256;
        const int r = f >> 4, col = (f & 15) * 4;
        float4 v = *(const float4*)(Qb + r * 64 + col);
        Qs[r][col]     = f2t(v.x); Qs[r][col + 1] = f2t(v.y);
        Qs[r][col + 2] = f2t(v.z); Qs[r][col + 3] = f2t(v.w);
    }

    CP_WAIT0();
    __syncthreads();

    float O[2][8][4] = {};
    float mr0[2] = {-1e30f, -1e30f}, mr1[2] = {-1e30f, -1e30f};
    float lr0[2] = {0.f, 0.f},       lr1[2] = {0.f, 0.f};

    for (int kt = 0; kt < 32; kt++) {
        const int s = kt & 1;
        const unsigned (*Ksc)[68] = (const unsigned(*)[68])(sh + KS_OFF + s * 4352);
        const unsigned (*Vsc)[72] = (const unsigned(*)[72])(sh + VS_OFF + s * 4608);

        // prefetch next K/V tile into the alternate stage
        if (kt < 31) {
            const int s1 = s ^ 1;
            const float* Kn = Kb + (size_t)(kt + 1) * 64 * 64;
            const float* Vn = Vb + (size_t)(kt + 1) * 64 * 64;
            #pragma unroll
            for (int i = 0; i < 4; i++) {
                CP_ASYNC16(sbase + (KS_OFF + s1*4352 + rr[i]*68 + cc4[i]) * 4, Kn + rr[i]*64 + cc4[i]);
                CP_ASYNC16(sbase + (VS_OFF + s1*4608 + rr[i]*72 + cc4[i]) * 4, Vn + rr[i]*64 + cc4[i]);
            }
            CP_COMMIT();
        }

        // ---- QK^T + softmax + P staging, one 16-row m-subtile at a time ----
        #pragma unroll
        for (int t = 0; t < 2; t++) {
            const int rq = wr32 + t * 16;
            float sc[8][4] = {};
            #pragma unroll
            for (int d = 0; d < 8; d++) {
                const int k8 = d * 8;
                const unsigned a0 = Qs[rq + g][k8 + c];
                const unsigned a1 = Qs[rq + g + 8][k8 + c];
                const unsigned a2 = Qs[rq + g][k8 + c + 4];
                const unsigned a3 = Qs[rq + g + 8][k8 + c + 4];
                #pragma unroll
                for (int ni = 0; ni < 8; ni++) {
                    const unsigned b0 = Ksc[ni * 8 + g][k8 + c];
                    const unsigned b1 = Ksc[ni * 8 + g][k8 + c + 4];
                    mma8(sc[ni], a0, a1, a2, a3, b0, b1);
                }
            }

            // softmax half 0 (row rq+g)
            {
                float mx = -1e30f;
                #pragma unroll
                for (int ni = 0; ni < 8; ni++) mx = fmaxf(mx, fmaxf(sc[ni][0], sc[ni][1]));
                mx = fmaxf(mx, __shfl_xor_sync(0xffffffffu, mx, 1));
                mx = fmaxf(mx, __shfl_xor_sync(0xffffffffu, mx, 2));
                const float mn = fmaxf(mr0[t], mx);
                const float corr = exp2f(mr0[t] - mn);
                mr0[t] = mn;
                float s_ = 0.f;
                #pragma unroll
                for (int ni = 0; ni < 8; ni++) {
                    sc[ni][0] = exp2f(sc[ni][0] - mn);
                    sc[ni][1] = exp2f(sc[ni][1] - mn);
                    s_ += sc[ni][0] + sc[ni][1];
                }
                s_ += __shfl_xor_sync(0xffffffffu, s_, 1);
                s_ += __shfl_xor_sync(0xffffffffu, s_, 2);
                lr0[t] = lr0[t] * corr + s_;
                #pragma unroll
                for (int ni = 0; ni < 8; ni++) { O[t][ni][0] *= corr; O[t][ni][1] *= corr; }
            }
            // softmax half 1 (row rq+g+8)
            {
                float mx = -1e30f;
                #pragma unroll
                for (int ni = 0; ni < 8; ni++) mx = fmaxf(mx, fmaxf(sc[ni][2], sc[ni][3]));
                mx = fmaxf(mx, __shfl_xor_sync(0xffffffffu, mx, 1));
                mx = fmaxf(mx, __shfl_xor_sync(0xffffffffu, mx, 2));
                const float mn = fmaxf(mr1[t], mx);
                const float corr = exp2f(mr1[t] - mn);
                mr1[t] = mn;
                float s_ = 0.f;
                #pragma unroll
                for (int ni = 0; ni < 8; ni++) {
                    sc[ni][2] = exp2f(sc[ni][2] - mn);
                    sc[ni][3] = exp2f(sc[ni][3] - mn);
                    s_ += sc[ni][2] + sc[ni][3];
                }
                s_ += __shfl_xor_sync(0xffffffffu, s_, 1);
                s_ += __shfl_xor_sync(0xffffffffu, s_, 2);
                lr1[t] = lr1[t] * corr + s_;
                #pragma unroll
                for (int ni = 0; ni < 8; ni++) { O[t][ni][2] *= corr; O[t][ni][3] *= corr; }
            }

            // stage P (warp-private rows)
            #pragma unroll
            for (int ni = 0; ni < 8; ni++) {
                const int cc = ni * 8 + c * 2;
                Ps[rq + g][cc]         = f2t(sc[ni][0]);
                Ps[rq + g][cc + 1]     = f2t(sc[ni][1]);
                Ps[rq + g + 8][cc]     = f2t(sc[ni][2]);
                Ps[rq + g + 8][cc + 1] = f2t(sc[ni][3]);
            }
        }
        __syncwarp();

        // ---- O += P @ V : V fragments loaded once per d, shared by both t ----
        #pragma unroll
        for (int d = 0; d < 8; d++) {
            const int k8 = d * 8;
            uint2 bv[8];
            #pragma unroll
            for (int ni = 0; ni < 8; ni++) {
                bv[ni].x = Vsc[k8 + c][ni * 8 + g];
                bv[ni].y = Vsc[k8 + c + 4][ni * 8 + g];
            }
            #pragma unroll
            for (int t = 0; t < 2; t++) {
                const int rq = wr32 + t * 16;
                const unsigned a0 = Ps[rq + g][k8 + c];
                const unsigned a1 = Ps[rq + g + 8][k8 + c];
                const unsigned a2 = Ps[rq + g][k8 + c + 4];
                const unsigned a3 = Ps[rq + g + 8][k8 + c + 4];
                #pragma unroll
                for (int ni = 0; ni < 8; ni++)
                    mma8(O[t][ni], a0, a1, a2, a3, bv[ni].x, bv[ni].y);
            }
        }

        CP_WAIT0();
        __syncthreads();
    }

    // Normalize + write [B,S,D]
    const int b_ = bh >> 3, h_ = bh & 7;
    #pragma unroll
    for (int t = 0; t < 2; t++) {
        const float inv0 = 1.0f / lr0[t], inv1 = 1.0f / lr1[t];
        const int s0 = qt * 256 + wr32 + t * 16 + g;
        float* o0 = Out + ((size_t)(b_ * SS + s0)) * DD + h_ * 64;
        float* o1 = o0 + 8 * DD;
        #pragma unroll
        for (int ni = 0; ni < 8; ni++) {
            const int cc = ni * 8 + c * 2;
            o0[cc]     = O[t][ni][0] * inv0;
            o0[cc + 1] = O[t][ni][1] * inv0;
            o1[cc]     = O[t][ni][2] * inv1;
            o1[cc + 1] = O[t][ni][3] * inv1;
        }
    }
}

// ---------------------------------------------------------------------------

extern "C" void kernel_launch(void* const* d_in, const int* in_sizes, int n_in,
                              void* d_out, int out_size) {
    const float* x  = (const float*)d_in[0];
    const float* Wq = (const float*)d_in[1];
    const float* bq = (const float*)d_in[2];
    const float* Wk = (const float*)d_in[3];
    const float* bk = (const float*)d_in[4];
    const float* Wv = (const float*)d_in[5];
    const float* bv = (const float*)d_in[6];
    const float* Wo = (const float*)d_in[7];
    const float* bo = (const float*)d_in[8];
    float* out = (float*)d_out;

    float *Q, *K, *V, *attn;
    cudaGetSymbolAddress((void**)&Q, g_Q);
    cudaGetSymbolAddress((void**)&K, g_K);
    cudaGetSymbolAddress((void**)&V, g_V);
    cudaGetSymbolAddress((void**)&attn, g_attn);

    const int proj_smem = (2 * 128 * 36 + 2 * 64 * 36) * 4;   // 55296 B
    const int attn_smem = 52736 * 4;                           // 210944 B
    cudaFuncSetAttribute(proj_kernel<0>, cudaFuncAttributeMaxDynamicSharedMemorySize, proj_smem);
    cudaFuncSetAttribute(proj_kernel<1>, cudaFuncAttributeMaxDynamicSharedMemorySize, proj_smem);
    cudaFuncSetAttribute(attn_kernel,    cudaFuncAttributeMaxDynamicSharedMemorySize, attn_smem);

    const dim3 gp(512 / 64, M_TOTAL / 128);   // (8, 32)

    // QKV projections; Q gets 1/sqrt(64) * log2(e) folded in (exp2 softmax)
    const float qalpha = 0.125f * 1.4426950408889634f;
    proj_kernel<1><<<gp, 256, proj_smem>>>(x, Wq, bq, Q, qalpha);
    proj_kernel<1><<<gp, 256, proj_smem>>>(x, Wk, bk, K, 1.0f);
    proj_kernel<1><<<gp, 256, proj_smem>>>(x, Wv, bv, V, 1.0f);

    attn_kernel<<<dim3(8, 16), 256, attn_smem>>>(Q, K, V, attn);

    proj_kernel<0><<<gp, 256, proj_smem>>>(attn, Wo, bo, out, 1.0f);
}

// round 11
// speedup vs baseline: 1.3912x; 1.3912x over previous
#include <cuda_runtime.h>
#include <math.h>

#define BB 2
#define SS 2048
#define DD 512
#define HH 8
#define DK 64
#define M_TOTAL (BB*SS)   // 4096

// Scratch (allocation-free)
__device__ float g_Q[BB*HH*SS*DK];
__device__ float g_K[BB*HH*SS*DK];
__device__ float g_V[BB*HH*SS*DK];
__device__ float g_attn[BB*SS*DD];

// ---------------------------------------------------------------------------
__device__ __forceinline__ unsigned f2t(float x) {
    unsigned r;
    asm("cvt.rna.tf32.f32 %0, %1;" : "=r"(r) : "f"(x));
    return r;
}

__device__ __forceinline__ void mma8(float* c,
                                     unsigned a0, unsigned a1, unsigned a2, unsigned a3,
                                     unsigned b0, unsigned b1) {
    asm volatile(
        "mma.sync.aligned.m16n8k8.row.col.f32.tf32.tf32.f32 "
        "{%0,%1,%2,%3}, {%4,%5,%6,%7}, {%8,%9}, {%0,%1,%2,%3};"
        : "+f"(c[0]), "+f"(c[1]), "+f"(c[2]), "+f"(c[3])
        : "r"(a0), "r"(a1), "r"(a2), "r"(a3), "r"(b0), "r"(b1));
}

#define CP_ASYNC16(smem_u32, gptr) \
    asm volatile("cp.async.cg.shared.global [%0], [%1], 16;" :: "r"(smem_u32), "l"(gptr))
#define CP_COMMIT()  asm volatile("cp.async.commit_group;" ::: "memory")
#define CP_WAIT0()   asm volatile("cp.async.wait_group 0;" ::: "memory")

// ---------------------------------------------------------------------------
// Single-pass TF32 GEMM with register-prefetch double buffering.
// C = (A @ W^T + bias) * alpha. Block 128x64, BK=32, 8 warps (4x2), pitch 36.
// MODE 0: row-major [M,N].  MODE 1: head-split [B,H,S,DK] + tf32-RNA rounding.
// ---------------------------------------------------------------------------
template<int MODE>
__global__ __launch_bounds__(256)
void proj_kernel(const float* __restrict__ A, const float* __restrict__ W,
                 const float* __restrict__ bias, float* __restrict__ C,
                 float alpha) {
    extern __shared__ unsigned sh[];
    unsigned (*Ab)[36] = (unsigned(*)[36])sh;              // 128x36
    unsigned (*Bb)[36] = (unsigned(*)[36])(sh + 128*36);   // 64x36

    const int tid  = threadIdx.x;
    const int lane = tid & 31;
    const int warp = tid >> 5;
    const int g = lane >> 2, c = lane & 3;
    const int wm = warp & 3, wn = warp >> 2;
    const int m0 = blockIdx.y * 128, n0 = blockIdx.x * 64;

    int ar[4], ac[4], wrr[2], wcc[2];
    #pragma unroll
    for (int i = 0; i < 4; i++) {
        const int f = tid + i * 256;
        ar[i] = f >> 3; ac[i] = (f & 7) * 4;
    }
    #pragma unroll
    for (int i = 0; i < 2; i++) {
        const int f = tid + i * 256;
        wrr[i] = f >> 3; wcc[i] = (f & 7) * 4;
    }

    float4 ra[4], rw[2];
    #pragma unroll
    for (int i = 0; i < 4; i++)
        ra[i] = *(const float4*)(A + (size_t)(m0 + ar[i]) * 512 + ac[i]);
    #pragma unroll
    for (int i = 0; i < 2; i++)
        rw[i] = *(const float4*)(W + (size_t)(n0 + wrr[i]) * 512 + wcc[i]);

    float acc[2][4][4] = {};

    for (int kt = 0; kt < 512; kt += 32) {
        __syncthreads();
        #pragma unroll
        for (int i = 0; i < 4; i++) {
            *(uint2*)&Ab[ar[i]][ac[i]]     = make_uint2(f2t(ra[i].x), f2t(ra[i].y));
            *(uint2*)&Ab[ar[i]][ac[i] + 2] = make_uint2(f2t(ra[i].z), f2t(ra[i].w));
        }
        #pragma unroll
        for (int i = 0; i < 2; i++) {
            *(uint2*)&Bb[wrr[i]][wcc[i]]     = make_uint2(f2t(rw[i].x), f2t(rw[i].y));
            *(uint2*)&Bb[wrr[i]][wcc[i] + 2] = make_uint2(f2t(rw[i].z), f2t(rw[i].w));
        }
        __syncthreads();

        if (kt + 32 < 512) {
            #pragma unroll
            for (int i = 0; i < 4; i++)
                ra[i] = *(const float4*)(A + (size_t)(m0 + ar[i]) * 512 + kt + 32 + ac[i]);
            #pragma unroll
            for (int i = 0; i < 2; i++)
                rw[i] = *(const float4*)(W + (size_t)(n0 + wrr[i]) * 512 + kt + 32 + wcc[i]);
        }

        #pragma unroll
        for (int d = 0; d < 4; d++) {
            const int k8 = d * 8;
            unsigned ab[2][4], bb[4][2];
            #pragma unroll
            for (int mi = 0; mi < 2; mi++) {
                const int rb = wm * 32 + mi * 16;
                ab[mi][0] = Ab[rb + g][k8 + c];     ab[mi][1] = Ab[rb + g + 8][k8 + c];
                ab[mi][2] = Ab[rb + g][k8 + c + 4]; ab[mi][3] = Ab[rb + g + 8][k8 + c + 4];
            }
            #pragma unroll
            for (int ni = 0; ni < 4; ni++) {
                const int cb = wn * 32 + ni * 8;
                bb[ni][0] = Bb[cb + g][k8 + c];  bb[ni][1] = Bb[cb + g][k8 + c + 4];
            }
            #pragma unroll
            for (int mi = 0; mi < 2; mi++)
                #pragma unroll
                for (int ni = 0; ni < 4; ni++)
                    mma8(acc[mi][ni], ab[mi][0], ab[mi][1], ab[mi][2], ab[mi][3], bb[ni][0], bb[ni][1]);
        }
    }

    #pragma unroll
    for (int mi = 0; mi < 2; mi++) {
        const int r0 = m0 + wm * 32 + mi * 16 + g;
        #pragma unroll
        for (int ni = 0; ni < 4; ni++) {
            const int cc = n0 + wn * 32 + ni * 8 + c * 2;
            const float b0 = bias[cc], b1 = bias[cc + 1];
            float v[4];
            v[0] = (acc[mi][ni][0] + b0) * alpha;
            v[1] = (acc[mi][ni][1] + b1) * alpha;
            v[2] = (acc[mi][ni][2] + b0) * alpha;
            v[3] = (acc[mi][ni][3] + b1) * alpha;
            #pragma unroll
            for (int p = 0; p < 2; p++) {
                const int m = r0 + p * 8;
                #pragma unroll
                for (int q = 0; q < 2; q++) {
                    const int n = cc + q;
                    float val = v[p * 2 + q];
                    if (MODE == 0) {
                        C[(size_t)m * 512 + n] = val;
                    } else {
                        val = __uint_as_float(f2t(val));   // pre-round for attn cp.async
                        const int b_ = m >> 11, s_ = m & 2047;
                        const int h_ = n >> 6, dk = n & 63;
                        C[(((size_t)(b_ * HH + h_)) * SS + s_) * DK + dk] = val;
                    }
                }
            }
        }
    }
}

// ---------------------------------------------------------------------------
// Flash attention: exact R7 config. 512 threads, 256-row q-tile, 16 warps
// (16 rows each), cp.async double-buffered K/V, exp2 softmax.
// smem (words): Qs[256][68] @0 | Ks[2][64][68] @17408 | Vs[2][64][72] @26112
//               | Ps[256][68] @35328  -> 52736 words = 210944 B
// ---------------------------------------------------------------------------
#define QS_OFF 0
#define KS_OFF 17408
#define VS_OFF 26112
#define PS_OFF 35328

__global__ __launch_bounds__(512)
void attn_kernel(const float* __restrict__ Q, const float* __restrict__ K,
                 const float* __restrict__ V, float* __restrict__ Out) {
    extern __shared__ unsigned sh[];
    unsigned (*Qs)[68] = (unsigned(*)[68])(sh + QS_OFF);
    unsigned (*Ps)[68] = (unsigned(*)[68])(sh + PS_OFF);

    const int tid  = threadIdx.x;
    const int lane = tid & 31;
    const int warp = tid >> 5;       // 0..15
    const int g = lane >> 2, c = lane & 3;
    const int wr = warp * 16;        // 0..240
    const int qt = blockIdx.x;       // 0..7
    const int bh = blockIdx.y;       // 0..15

    const float* Qb = Q + (size_t)bh * SS * DK + (size_t)qt * 256 * DK;
    const float* Kb = K + (size_t)bh * SS * DK;
    const float* Vb = V + (size_t)bh * SS * DK;

    const unsigned sbase = (unsigned)__cvta_generic_to_shared(sh);

    int rr[2], cc4[2];
    #pragma unroll
    for (int i = 0; i < 2; i++) {
        const int f = tid + i * 512;
        rr[i] = f >> 4;
        cc4[i] = (f & 15) * 4;
    }

    // prologue: stage 0 K/V
    #pragma unroll
    for (int i = 0; i < 2; i++) {
        CP_ASYNC16(sbase + (KS_OFF + rr[i]*68 + cc4[i]) * 4, Kb + rr[i]*64 + cc4[i]);
        CP_ASYNC16(sbase + (VS_OFF + rr[i]*72 + cc4[i]) * 4, Vb + rr[i]*64 + cc4[i]);
    }
    CP_COMMIT();

    // Q tile -> tf32 smem (256x64)
    #pragma unroll
    for (int i = 0; i < 8; i++) {
        const int f = tid + i * 512;
        const int r = f >> 4, col = (f & 15) * 4;
        float4 v = *(const float4*)(Qb + r * 64 + col);
        Qs[r][col]     = f2t(v.x); Qs[r][col + 1] = f2t(v.y);
        Qs[r][col + 2] = f2t(v.z); Qs[r][col + 3] = f2t(v.w);
    }

    CP_WAIT0();
    __syncthreads();

    float O[8][4] = {};
    float m0r = -1e30f, m1r = -1e30f, l0 = 0.f, l1 = 0.f;

    for (int kt = 0; kt < 32; kt++) {
        const int s = kt & 1;
        const unsigned (*Ksc)[68] = (const unsigned(*)[68])(sh + KS_OFF + s * 4352);
        const unsigned (*Vsc)[72] = (const unsigned(*)[72])(sh + VS_OFF + s * 4608);

        if (kt < 31) {
            const int s1 = s ^ 1;
            const float* Kn = Kb + (size_t)(kt + 1) * 64 * 64;
            const float* Vn = Vb + (size_t)(kt + 1) * 64 * 64;
            #pragma unroll
            for (int i = 0; i < 2; i++) {
                CP_ASYNC16(sbase + (KS_OFF + s1*4352 + rr[i]*68 + cc4[i]) * 4, Kn + rr[i]*64 + cc4[i]);
                CP_ASYNC16(sbase + (VS_OFF + s1*4608 + rr[i]*72 + cc4[i]) * 4, Vn + rr[i]*64 + cc4[i]);
            }
            CP_COMMIT();
        }

        // S = Q K^T (log2-domain scores; Q pre-scaled by 0.125*log2e)
        float sc[8][4] = {};
        #pragma unroll
        for (int d = 0; d < 8; d++) {
            const int k8 = d * 8;
            const unsigned a0 = Qs[wr + g][k8 + c];
            const unsigned a1 = Qs[wr + g + 8][k8 + c];
            const unsigned a2 = Qs[wr + g][k8 + c + 4];
            const unsigned a3 = Qs[wr + g + 8][k8 + c + 4];
            #pragma unroll
            for (int ni = 0; ni < 8; ni++) {
                const unsigned b0 = Ksc[ni * 8 + g][k8 + c];
                const unsigned b1 = Ksc[ni * 8 + g][k8 + c + 4];
                mma8(sc[ni], a0, a1, a2, a3, b0, b1);
            }
        }

        // Online softmax (base-2)
        {
            float mx = -1e30f;
            #pragma unroll
            for (int ni = 0; ni < 8; ni++) mx = fmaxf(mx, fmaxf(sc[ni][0], sc[ni][1]));
            mx = fmaxf(mx, __shfl_xor_sync(0xffffffffu, mx, 1));
            mx = fmaxf(mx, __shfl_xor_sync(0xffffffffu, mx, 2));
            const float mn = fmaxf(m0r, mx);
            const float corr = exp2f(m0r - mn);
            m0r = mn;
            float s_ = 0.f;
            #pragma unroll
            for (int ni = 0; ni < 8; ni++) {
                sc[ni][0] = exp2f(sc[ni][0] - mn);
                sc[ni][1] = exp2f(sc[ni][1] - mn);
                s_ += sc[ni][0] + sc[ni][1];
            }
            s_ += __shfl_xor_sync(0xffffffffu, s_, 1);
            s_ += __shfl_xor_sync(0xffffffffu, s_, 2);
            l0 = l0 * corr + s_;
            #pragma unroll
            for (int ni = 0; ni < 8; ni++) { O[ni][0] *= corr; O[ni][1] *= corr; }
        }
        {
            float mx = -1e30f;
            #pragma unroll
            for (int ni = 0; ni < 8; ni++) mx = fmaxf(mx, fmaxf(sc[ni][2], sc[ni][3]));
            mx = fmaxf(mx, __shfl_xor_sync(0xffffffffu, mx, 1));
            mx = fmaxf(mx, __shfl_xor_sync(0xffffffffu, mx, 2));
            const float mn = fmaxf(m1r, mx);
            const float corr = exp2f(m1r - mn);
            m1r = mn;
            float s_ = 0.f;
            #pragma unroll
            for (int ni = 0; ni < 8; ni++) {
                sc[ni][2] = exp2f(sc[ni][2] - mn);
                sc[ni][3] = exp2f(sc[ni][3] - mn);
                s_ += sc[ni][2] + sc[ni][3];
            }
            s_ += __shfl_xor_sync(0xffffffffu, s_, 1);
            s_ += __shfl_xor_sync(0xffffffffu, s_, 2);
            l1 = l1 * corr + s_;
            #pragma unroll
            for (int ni = 0; ni < 8; ni++) { O[ni][2] *= corr; O[ni][3] *= corr; }
        }

        // Stage P (warp-private rows)
        #pragma unroll
        for (int ni = 0; ni < 8; ni++) {
            const int cc = ni * 8 + c * 2;
            Ps[wr + g][cc]         = f2t(sc[ni][0]);
            Ps[wr + g][cc + 1]     = f2t(sc[ni][1]);
            Ps[wr + g + 8][cc]     = f2t(sc[ni][2]);
            Ps[wr + g + 8][cc + 1] = f2t(sc[ni][3]);
        }
        __syncwarp();

        // O += P @ V
        #pragma unroll
        for (int d = 0; d < 8; d++) {
            const int k8 = d * 8;
            const unsigned a0 = Ps[wr + g][k8 + c];
            const unsigned a1 = Ps[wr + g + 8][k8 + c];
            const unsigned a2 = Ps[wr + g][k8 + c + 4];
            const unsigned a3 = Ps[wr + g + 8][k8 + c + 4];
            #pragma unroll
            for (int ni = 0; ni < 8; ni++) {
                const unsigned b0 = Vsc[k8 + c][ni * 8 + g];
                const unsigned b1 = Vsc[k8 + c + 4][ni * 8 + g];
                mma8(O[ni], a0, a1, a2, a3, b0, b1);
            }
        }

        CP_WAIT0();
        __syncthreads();
    }

    // Normalize + write [B,S,D]
    const int b_ = bh >> 3, h_ = bh & 7;
    const float inv0 = 1.0f / l0, inv1 = 1.0f / l1;
    const int s0 = qt * 256 + wr + g;
    float* o0 = Out + ((size_t)(b_ * SS + s0)) * DD + h_ * 64;
    float* o1 = o0 + 8 * DD;
    #pragma unroll
    for (int ni = 0; ni < 8; ni++) {
        const int cc = ni * 8 + c * 2;
        o0[cc]     = O[ni][0] * inv0;
        o0[cc + 1] = O[ni][1] * inv0;
        o1[cc]     = O[ni][2] * inv1;
        o1[cc + 1] = O[ni][3] * inv1;
    }
}

// ---------------------------------------------------------------------------

extern "C" void kernel_launch(void* const* d_in, const int* in_sizes, int n_in,
                              void* d_out, int out_size) {
    const float* x  = (const float*)d_in[0];
    const float* Wq = (const float*)d_in[1];
    const float* bq = (const float*)d_in[2];
    const float* Wk = (const float*)d_in[3];
    const float* bk = (const float*)d_in[4];
    const float* Wv = (const float*)d_in[5];
    const float* bv = (const float*)d_in[6];
    const float* Wo = (const float*)d_in[7];
    const float* bo = (const float*)d_in[8];
    float* out = (float*)d_out;

    float *Q, *K, *V, *attn;
    cudaGetSymbolAddress((void**)&Q, g_Q);
    cudaGetSymbolAddress((void**)&K, g_K);
    cudaGetSymbolAddress((void**)&V, g_V);
    cudaGetSymbolAddress((void**)&attn, g_attn);

    const int proj_smem = (128 * 36 + 64 * 36) * 4;   // 27648 B
    const int attn_smem = 52736 * 4;                   // 210944 B
    cudaFuncSetAttribute(proj_kernel<0>, cudaFuncAttributeMaxDynamicSharedMemorySize, proj_smem);
    cudaFuncSetAttribute(proj_kernel<1>, cudaFuncAttributeMaxDynamicSharedMemorySize, proj_smem);
    cudaFuncSetAttribute(attn_kernel,    cudaFuncAttributeMaxDynamicSharedMemorySize, attn_smem);

    const dim3 gp(512 / 64, M_TOTAL / 128);   // (8, 32)

    // QKV projections; Q gets 1/sqrt(64) * log2(e) folded in (exp2 softmax)
    const float qalpha = 0.125f * 1.4426950408889634f;
    proj_kernel<1><<<gp, 256, proj_smem>>>(x, Wq, bq, Q, qalpha);
    proj_kernel<1><<<gp, 256, proj_smem>>>(x, Wk, bk, K, 1.0f);
    proj_kernel<1><<<gp, 256, proj_smem>>>(x, Wv, bv, V, 1.0f);

    attn_kernel<<<dim3(8, 16), 512, attn_smem>>>(Q, K, V, attn);

    proj_kernel<0><<<gp, 256, proj_smem>>>(attn, Wo, bo, out, 1.0f);
}

// round 12
// speedup vs baseline: 1.4257x; 1.0248x over previous
#include <cuda_runtime.h>
#include <math.h>

#define BB 2
#define SS 2048
#define DD 512
#define HH 8
#define DK 64
#define M_TOTAL (BB*SS)   // 4096

// Scratch (allocation-free)
__device__ float g_Q[BB*HH*SS*DK];
__device__ float g_K[BB*HH*SS*DK];
__device__ float g_V[BB*HH*SS*DK];
__device__ float g_attn[BB*SS*DD];

// ---------------------------------------------------------------------------
__device__ __forceinline__ unsigned f2t(float x) {
    unsigned r;
    asm("cvt.rna.tf32.f32 %0, %1;" : "=r"(r) : "f"(x));
    return r;
}

__device__ __forceinline__ void mma8(float* c,
                                     unsigned a0, unsigned a1, unsigned a2, unsigned a3,
                                     unsigned b0, unsigned b1) {
    asm volatile(
        "mma.sync.aligned.m16n8k8.row.col.f32.tf32.tf32.f32 "
        "{%0,%1,%2,%3}, {%4,%5,%6,%7}, {%8,%9}, {%0,%1,%2,%3};"
        : "+f"(c[0]), "+f"(c[1]), "+f"(c[2]), "+f"(c[3])
        : "r"(a0), "r"(a1), "r"(a2), "r"(a3), "r"(b0), "r"(b1));
}

#define CP_ASYNC16(smem_u32, gptr) \
    asm volatile("cp.async.cg.shared.global [%0], [%1], 16;" :: "r"(smem_u32), "l"(gptr))
#define CP_COMMIT()  asm volatile("cp.async.commit_group;" ::: "memory")
#define CP_WAIT0()   asm volatile("cp.async.wait_group 0;" ::: "memory")

// ---------------------------------------------------------------------------
// Single-pass TF32 GEMM body with register-prefetch double buffering and
// conflict-free STS.128 smem stores.
// C = (A @ W^T + bias) * alpha. Block 128x64, BK=32, 8 warps (4x2), pitch 36.
// MODE 0: row-major [M,N].  MODE 1: head-split [B,H,S,DK] + tf32-RNA rounding.
// ---------------------------------------------------------------------------
template<int MODE>
__device__ __forceinline__
void proj_body(const float* __restrict__ A, const float* __restrict__ W,
               const float* __restrict__ bias, float* __restrict__ C,
               float alpha, int m0, int n0, unsigned* sh) {
    unsigned (*Ab)[36] = (unsigned(*)[36])sh;              // 128x36
    unsigned (*Bb)[36] = (unsigned(*)[36])(sh + 128*36);   // 64x36

    const int tid  = threadIdx.x;
    const int lane = tid & 31;
    const int warp = tid >> 5;
    const int g = lane >> 2, c = lane & 3;
    const int wm = warp & 3, wn = warp >> 2;

    int ar[4], ac[4], wrr[2], wcc[2];
    #pragma unroll
    for (int i = 0; i < 4; i++) {
        const int f = tid + i * 256;
        ar[i] = f >> 3; ac[i] = (f & 7) * 4;
    }
    #pragma unroll
    for (int i = 0; i < 2; i++) {
        const int f = tid + i * 256;
        wrr[i] = f >> 3; wcc[i] = (f & 7) * 4;
    }

    float4 ra[4], rw[2];
    #pragma unroll
    for (int i = 0; i < 4; i++)
        ra[i] = *(const float4*)(A + (size_t)(m0 + ar[i]) * 512 + ac[i]);
    #pragma unroll
    for (int i = 0; i < 2; i++)
        rw[i] = *(const float4*)(W + (size_t)(n0 + wrr[i]) * 512 + wcc[i]);

    float acc[2][4][4] = {};

    for (int kt = 0; kt < 512; kt += 32) {
        __syncthreads();
        // conflict-free STS.128 (each 128B phase = one full row = 32 banks)
        #pragma unroll
        for (int i = 0; i < 4; i++) {
            *(uint4*)&Ab[ar[i]][ac[i]] =
                make_uint4(f2t(ra[i].x), f2t(ra[i].y), f2t(ra[i].z), f2t(ra[i].w));
        }
        #pragma unroll
        for (int i = 0; i < 2; i++) {
            *(uint4*)&Bb[wrr[i]][wcc[i]] =
                make_uint4(f2t(rw[i].x), f2t(rw[i].y), f2t(rw[i].z), f2t(rw[i].w));
        }
        __syncthreads();

        if (kt + 32 < 512) {
            #pragma unroll
            for (int i = 0; i < 4; i++)
                ra[i] = *(const float4*)(A + (size_t)(m0 + ar[i]) * 512 + kt + 32 + ac[i]);
            #pragma unroll
            for (int i = 0; i < 2; i++)
                rw[i] = *(const float4*)(W + (size_t)(n0 + wrr[i]) * 512 + kt + 32 + wcc[i]);
        }

        #pragma unroll
        for (int d = 0; d < 4; d++) {
            const int k8 = d * 8;
            unsigned ab[2][4], bb[4][2];
            #pragma unroll
            for (int mi = 0; mi < 2; mi++) {
                const int rb = wm * 32 + mi * 16;
                ab[mi][0] = Ab[rb + g][k8 + c];     ab[mi][1] = Ab[rb + g + 8][k8 + c];
                ab[mi][2] = Ab[rb + g][k8 + c + 4]; ab[mi][3] = Ab[rb + g + 8][k8 + c + 4];
            }
            #pragma unroll
            for (int ni = 0; ni < 4; ni++) {
                const int cb = wn * 32 + ni * 8;
                bb[ni][0] = Bb[cb + g][k8 + c];  bb[ni][1] = Bb[cb + g][k8 + c + 4];
            }
            #pragma unroll
            for (int mi = 0; mi < 2; mi++)
                #pragma unroll
                for (int ni = 0; ni < 4; ni++)
                    mma8(acc[mi][ni], ab[mi][0], ab[mi][1], ab[mi][2], ab[mi][3], bb[ni][0], bb[ni][1]);
        }
    }

    #pragma unroll
    for (int mi = 0; mi < 2; mi++) {
        const int r0 = m0 + wm * 32 + mi * 16 + g;
        #pragma unroll
        for (int ni = 0; ni < 4; ni++) {
            const int cc = n0 + wn * 32 + ni * 8 + c * 2;
            const float b0 = bias[cc], b1 = bias[cc + 1];
            float v[4];
            v[0] = (acc[mi][ni][0] + b0) * alpha;
            v[1] = (acc[mi][ni][1] + b1) * alpha;
            v[2] = (acc[mi][ni][2] + b0) * alpha;
            v[3] = (acc[mi][ni][3] + b1) * alpha;
            #pragma unroll
            for (int p = 0; p < 2; p++) {
                const int m = r0 + p * 8;
                #pragma unroll
                for (int q = 0; q < 2; q++) {
                    const int n = cc + q;
                    float val = v[p * 2 + q];
                    if (MODE == 0) {
                        C[(size_t)m * 512 + n] = val;
                    } else {
                        val = __uint_as_float(f2t(val));   // pre-round for attn cp.async
                        const int b_ = m >> 11, s_ = m & 2047;
                        const int h_ = n >> 6, dk = n & 63;
                        C[(((size_t)(b_ * HH + h_)) * SS + s_) * DK + dk] = val;
                    }
                }
            }
        }
    }
}

// Fused Q/K/V projection: blockIdx.z selects weight/bias/output. NO min-blocks cap.
__global__ __launch_bounds__(256)
void qkv_proj_kernel(const float* __restrict__ x,
                     const float* __restrict__ Wq, const float* __restrict__ bq,
                     const float* __restrict__ Wk, const float* __restrict__ bk,
                     const float* __restrict__ Wv, const float* __restrict__ bv,
                     float qalpha) {
    extern __shared__ unsigned sh[];
    const int z = blockIdx.z;
    const float* W    = (z == 0) ? Wq : (z == 1) ? Wk : Wv;
    const float* bias = (z == 0) ? bq : (z == 1) ? bk : bv;
    float* C = (z == 0) ? g_Q : (z == 1) ? g_K : g_V;
    const float alpha = (z == 0) ? qalpha : 1.0f;
    proj_body<1>(x, W, bias, C, alpha, blockIdx.y * 128, blockIdx.x * 64, sh);
}

__global__ __launch_bounds__(256)
void out_proj_kernel(const float* __restrict__ Wo, const float* __restrict__ bo,
                     float* __restrict__ out) {
    extern __shared__ unsigned sh[];
    proj_body<0>(g_attn, Wo, bo, out, 1.0f, blockIdx.y * 128, blockIdx.x * 64, sh);
}

// ---------------------------------------------------------------------------
// Flash attention: exact R7/R10 config (verified 144.8us). 512 threads,
// 256-row q-tile, 16 warps (16 rows each), cp.async double-buffered K/V,
// exp2 softmax. Only change: Q-prologue store is now STS.128.
// smem (words): Qs[256][68] @0 | Ks[2][64][68] @17408 | Vs[2][64][72] @26112
//               | Ps[256][68] @35328  -> 52736 words = 210944 B
// ---------------------------------------------------------------------------
#define QS_OFF 0
#define KS_OFF 17408
#define VS_OFF 26112
#define PS_OFF 35328

__global__ __launch_bounds__(512)
void attn_kernel(const float* __restrict__ Q, const float* __restrict__ K,
                 const float* __restrict__ V, float* __restrict__ Out) {
    extern __shared__ unsigned sh[];
    unsigned (*Qs)[68] = (unsigned(*)[68])(sh + QS_OFF);
    unsigned (*Ps)[68] = (unsigned(*)[68])(sh + PS_OFF);

    const int tid  = threadIdx.x;
    const int lane = tid & 31;
    const int warp = tid >> 5;       // 0..15
    const int g = lane >> 2, c = lane & 3;
    const int wr = warp * 16;        // 0..240
    const int qt = blockIdx.x;       // 0..7
    const int bh = blockIdx.y;       // 0..15

    const float* Qb = Q + (size_t)bh * SS * DK + (size_t)qt * 256 * DK;
    const float* Kb = K + (size_t)bh * SS * DK;
    const float* Vb = V + (size_t)bh * SS * DK;

    const unsigned sbase = (unsigned)__cvta_generic_to_shared(sh);

    int rr[2], cc4[2];
    #pragma unroll
    for (int i = 0; i < 2; i++) {
        const int f = tid + i * 512;
        rr[i] = f >> 4;
        cc4[i] = (f & 15) * 4;
    }

    // prologue: stage 0 K/V
    #pragma unroll
    for (int i = 0; i < 2; i++) {
        CP_ASYNC16(sbase + (KS_OFF + rr[i]*68 + cc4[i]) * 4, Kb + rr[i]*64 + cc4[i]);
        CP_ASYNC16(sbase + (VS_OFF + rr[i]*72 + cc4[i]) * 4, Vb + rr[i]*64 + cc4[i]);
    }
    CP_COMMIT();

    // Q tile -> tf32 smem (256x64), STS.128
    #pragma unroll
    for (int i = 0; i < 8; i++) {
        const int f = tid + i * 512;
        const int r = f >> 4, col = (f & 15) * 4;
        float4 v = *(const float4*)(Qb + r * 64 + col);
        *(uint4*)&Qs[r][col] = make_uint4(f2t(v.x), f2t(v.y), f2t(v.z), f2t(v.w));
    }

    CP_WAIT0();
    __syncthreads();

    float O[8][4] = {};
    float m0r = -1e30f, m1r = -1e30f, l0 = 0.f, l1 = 0.f;

    for (int kt = 0; kt < 32; kt++) {
        const int s = kt & 1;
        const unsigned (*Ksc)[68] = (const unsigned(*)[68])(sh + KS_OFF + s * 4352);
        const unsigned (*Vsc)[72] = (const unsigned(*)[72])(sh + VS_OFF + s * 4608);

        if (kt < 31) {
            const int s1 = s ^ 1;
            const float* Kn = Kb + (size_t)(kt + 1) * 64 * 64;
            const float* Vn = Vb + (size_t)(kt + 1) * 64 * 64;
            #pragma unroll
            for (int i = 0; i < 2; i++) {
                CP_ASYNC16(sbase + (KS_OFF + s1*4352 + rr[i]*68 + cc4[i]) * 4, Kn + rr[i]*64 + cc4[i]);
                CP_ASYNC16(sbase + (VS_OFF + s1*4608 + rr[i]*72 + cc4[i]) * 4, Vn + rr[i]*64 + cc4[i]);
            }
            CP_COMMIT();
        }

        // S = Q K^T (log2-domain scores; Q pre-scaled by 0.125*log2e)
        float sc[8][4] = {};
        #pragma unroll
        for (int d = 0; d < 8; d++) {
            const int k8 = d * 8;
            const unsigned a0 = Qs[wr + g][k8 + c];
            const unsigned a1 = Qs[wr + g + 8][k8 + c];
            const unsigned a2 = Qs[wr + g][k8 + c + 4];
            const unsigned a3 = Qs[wr + g + 8][k8 + c + 4];
            #pragma unroll
            for (int ni = 0; ni < 8; ni++) {
                const unsigned b0 = Ksc[ni * 8 + g][k8 + c];
                const unsigned b1 = Ksc[ni * 8 + g][k8 + c + 4];
                mma8(sc[ni], a0, a1, a2, a3, b0, b1);
            }
        }

        // Online softmax (base-2)
        {
            float mx = -1e30f;
            #pragma unroll
            for (int ni = 0; ni < 8; ni++) mx = fmaxf(mx, fmaxf(sc[ni][0], sc[ni][1]));
            mx = fmaxf(mx, __shfl_xor_sync(0xffffffffu, mx, 1));
            mx = fmaxf(mx, __shfl_xor_sync(0xffffffffu, mx, 2));
            const float mn = fmaxf(m0r, mx);
            const float corr = exp2f(m0r - mn);
            m0r = mn;
            float s_ = 0.f;
            #pragma unroll
            for (int ni = 0; ni < 8; ni++) {
                sc[ni][0] = exp2f(sc[ni][0] - mn);
                sc[ni][1] = exp2f(sc[ni][1] - mn);
                s_ += sc[ni][0] + sc[ni][1];
            }
            s_ += __shfl_xor_sync(0xffffffffu, s_, 1);
            s_ += __shfl_xor_sync(0xffffffffu, s_, 2);
            l0 = l0 * corr + s_;
            #pragma unroll
            for (int ni = 0; ni < 8; ni++) { O[ni][0] *= corr; O[ni][1] *= corr; }
        }
        {
            float mx = -1e30f;
            #pragma unroll
            for (int ni = 0; ni < 8; ni++) mx = fmaxf(mx, fmaxf(sc[ni][2], sc[ni][3]));
            mx = fmaxf(mx, __shfl_xor_sync(0xffffffffu, mx, 1));
            mx = fmaxf(mx, __shfl_xor_sync(0xffffffffu, mx, 2));
            const float mn = fmaxf(m1r, mx);
            const float corr = exp2f(m1r - mn);
            m1r = mn;
            float s_ = 0.f;
            #pragma unroll
            for (int ni = 0; ni < 8; ni++) {
                sc[ni][2] = exp2f(sc[ni][2] - mn);
                sc[ni][3] = exp2f(sc[ni][3] - mn);
                s_ += sc[ni][2] + sc[ni][3];
            }
            s_ += __shfl_xor_sync(0xffffffffu, s_, 1);
            s_ += __shfl_xor_sync(0xffffffffu, s_, 2);
            l1 = l1 * corr + s_;
            #pragma unroll
            for (int ni = 0; ni < 8; ni++) { O[ni][2] *= corr; O[ni][3] *= corr; }
        }

        // Stage P (warp-private rows)
        #pragma unroll
        for (int ni = 0; ni < 8; ni++) {
            const int cc = ni * 8 + c * 2;
            Ps[wr + g][cc]         = f2t(sc[ni][0]);
            Ps[wr + g][cc + 1]     = f2t(sc[ni][1]);
            Ps[wr + g + 8][cc]     = f2t(sc[ni][2]);
            Ps[wr + g + 8][cc + 1] = f2t(sc[ni][3]);
        }
        __syncwarp();

        // O += P @ V
        #pragma unroll
        for (int d = 0; d < 8; d++) {
            const int k8 = d * 8;
            const unsigned a0 = Ps[wr + g][k8 + c];
            const unsigned a1 = Ps[wr + g + 8][k8 + c];
            const unsigned a2 = Ps[wr + g][k8 + c + 4];
            const unsigned a3 = Ps[wr + g + 8][k8 + c + 4];
            #pragma unroll
            for (int ni = 0; ni < 8; ni++) {
                const unsigned b0 = Vsc[k8 + c][ni * 8 + g];
                const unsigned b1 = Vsc[k8 + c + 4][ni * 8 + g];
                mma8(O[ni], a0, a1, a2, a3, b0, b1);
            }
        }

        CP_WAIT0();
        __syncthreads();
    }

    // Normalize + write [B,S,D]
    const int b_ = bh >> 3, h_ = bh & 7;
    const float inv0 = 1.0f / l0, inv1 = 1.0f / l1;
    const int s0 = qt * 256 + wr + g;
    float* o0 = Out + ((size_t)(b_ * SS + s0)) * DD + h_ * 64;
    float* o1 = o0 + 8 * DD;
    #pragma unroll
    for (int ni = 0; ni < 8; ni++) {
        const int cc = ni * 8 + c * 2;
        o0[cc]     = O[ni][0] * inv0;
        o0[cc + 1] = O[ni][1] * inv0;
        o1[cc]     = O[ni][2] * inv1;
        o1[cc + 1] = O[ni][3] * inv1;
    }
}

// ---------------------------------------------------------------------------

extern "C" void kernel_launch(void* const* d_in, const int* in_sizes, int n_in,
                              void* d_out, int out_size) {
    const float* x  = (const float*)d_in[0];
    const float* Wq = (const float*)d_in[1];
    const float* bq = (const float*)d_in[2];
    const float* Wk = (const float*)d_in[3];
    const float* bk = (const float*)d_in[4];
    const float* Wv = (const float*)d_in[5];
    const float* bv = (const float*)d_in[6];
    const float* Wo = (const float*)d_in[7];
    const float* bo = (const float*)d_in[8];
    float* out = (float*)d_out;

    float *Q, *K, *V, *attn;
    cudaGetSymbolAddress((void**)&Q, g_Q);
    cudaGetSymbolAddress((void**)&K, g_K);
    cudaGetSymbolAddress((void**)&V, g_V);
    cudaGetSymbolAddress((void**)&attn, g_attn);

    const int proj_smem = (128 * 36 + 64 * 36) * 4;   // 27648 B
    const int attn_smem = 52736 * 4;                   // 210944 B
    cudaFuncSetAttribute(qkv_proj_kernel, cudaFuncAttributeMaxDynamicSharedMemorySize, proj_smem);
    cudaFuncSetAttribute(out_proj_kernel, cudaFuncAttributeMaxDynamicSharedMemorySize, proj_smem);
    cudaFuncSetAttribute(attn_kernel,     cudaFuncAttributeMaxDynamicSharedMemorySize, attn_smem);

    // Fused QKV; Q gets 1/sqrt(64) * log2(e) folded in (exp2 softmax)
    const float qalpha = 0.125f * 1.4426950408889634f;
    qkv_proj_kernel<<<dim3(8, 32, 3), 256, proj_smem>>>(x, Wq, bq, Wk, bk, Wv, bv, qalpha);

    attn_kernel<<<dim3(8, 16), 512, attn_smem>>>(Q, K, V, attn);

    out_proj_kernel<<<dim3(8, 32), 256, proj_smem>>>(Wo, bo, out);
}

// round 13
// speedup vs baseline: 1.7626x; 1.2364x over previous
#include <cuda_runtime.h>
#include <cuda_bf16.h>
#include <math.h>

#define BB 2
#define SS 2048
#define DD 512
#define HH 8
#define DK 64
#define M_TOTAL (BB*SS)   // 4096

// Scratch (allocation-free)
__device__ float g_Q[BB*HH*SS*DK];
__device__ float g_K[BB*HH*SS*DK];
__device__ __nv_bfloat16 g_Vt[BB*HH*DK*SS];   // transposed: [bh][dk][s]
__device__ float g_attn[BB*SS*DD];

// ---------------------------------------------------------------------------
__device__ __forceinline__ unsigned f2t(float x) {
    unsigned r;
    asm("cvt.rna.tf32.f32 %0, %1;" : "=r"(r) : "f"(x));
    return r;
}

__device__ __forceinline__ unsigned packbf(float lo, float hi) {
    unsigned r;
    asm("cvt.rn.bf16x2.f32 %0, %1, %2;" : "=r"(r) : "f"(hi), "f"(lo));
    return r;
}

__device__ __forceinline__ void mma8(float* c,
                                     unsigned a0, unsigned a1, unsigned a2, unsigned a3,
                                     unsigned b0, unsigned b1) {
    asm volatile(
        "mma.sync.aligned.m16n8k8.row.col.f32.tf32.tf32.f32 "
        "{%0,%1,%2,%3}, {%4,%5,%6,%7}, {%8,%9}, {%0,%1,%2,%3};"
        : "+f"(c[0]), "+f"(c[1]), "+f"(c[2]), "+f"(c[3])
        : "r"(a0), "r"(a1), "r"(a2), "r"(a3), "r"(b0), "r"(b1));
}

__device__ __forceinline__ void mma16(float* c,
                                      unsigned a0, unsigned a1, unsigned a2, unsigned a3,
                                      unsigned b0, unsigned b1) {
    asm volatile(
        "mma.sync.aligned.m16n8k16.row.col.f32.bf16.bf16.f32 "
        "{%0,%1,%2,%3}, {%4,%5,%6,%7}, {%8,%9}, {%0,%1,%2,%3};"
        : "+f"(c[0]), "+f"(c[1]), "+f"(c[2]), "+f"(c[3])
        : "r"(a0), "r"(a1), "r"(a2), "r"(a3), "r"(b0), "r"(b1));
}

#define CP_ASYNC16(smem_u32, gptr) \
    asm volatile("cp.async.cg.shared.global [%0], [%1], 16;" :: "r"(smem_u32), "l"(gptr))
#define CP_COMMIT()  asm volatile("cp.async.commit_group;" ::: "memory")
#define CP_WAIT0()   asm volatile("cp.async.wait_group 0;" ::: "memory")

// ---------------------------------------------------------------------------
// Single-pass TF32 GEMM body, register-prefetch double buffering, STS.128.
// C = (A @ W^T + bias) * alpha. Block 128x64, BK=32, 8 warps (4x2), pitch 36.
// MODE 0: row-major [M,N] fp32.
// MODE 1: head-split [B,H,S,DK] fp32 + tf32-RNA pre-round.
// MODE 2: head-split TRANSPOSED [B,H,DK,S] bf16 (for attn V).
// ---------------------------------------------------------------------------
template<int MODE>
__device__ __forceinline__
void proj_body(const float* __restrict__ A, const float* __restrict__ W,
               const float* __restrict__ bias, float* __restrict__ C,
               float alpha, int m0, int n0, unsigned* sh) {
    unsigned (*Ab)[36] = (unsigned(*)[36])sh;              // 128x36
    unsigned (*Bb)[36] = (unsigned(*)[36])(sh + 128*36);   // 64x36

    const int tid  = threadIdx.x;
    const int lane = tid & 31;
    const int warp = tid >> 5;
    const int g = lane >> 2, c = lane & 3;
    const int wm = warp & 3, wn = warp >> 2;

    int ar[4], ac[4], wrr[2], wcc[2];
    #pragma unroll
    for (int i = 0; i < 4; i++) {
        const int f = tid + i * 256;
        ar[i] = f >> 3; ac[i] = (f & 7) * 4;
    }
    #pragma unroll
    for (int i = 0; i < 2; i++) {
        const int f = tid + i * 256;
        wrr[i] = f >> 3; wcc[i] = (f & 7) * 4;
    }

    float4 ra[4], rw[2];
    #pragma unroll
    for (int i = 0; i < 4; i++)
        ra[i] = *(const float4*)(A + (size_t)(m0 + ar[i]) * 512 + ac[i]);
    #pragma unroll
    for (int i = 0; i < 2; i++)
        rw[i] = *(const float4*)(W + (size_t)(n0 + wrr[i]) * 512 + wcc[i]);

    float acc[2][4][4] = {};

    for (int kt = 0; kt < 512; kt += 32) {
        __syncthreads();
        #pragma unroll
        for (int i = 0; i < 4; i++) {
            *(uint4*)&Ab[ar[i]][ac[i]] =
                make_uint4(f2t(ra[i].x), f2t(ra[i].y), f2t(ra[i].z), f2t(ra[i].w));
        }
        #pragma unroll
        for (int i = 0; i < 2; i++) {
            *(uint4*)&Bb[wrr[i]][wcc[i]] =
                make_uint4(f2t(rw[i].x), f2t(rw[i].y), f2t(rw[i].z), f2t(rw[i].w));
        }
        __syncthreads();

        if (kt + 32 < 512) {
            #pragma unroll
            for (int i = 0; i < 4; i++)
                ra[i] = *(const float4*)(A + (size_t)(m0 + ar[i]) * 512 + kt + 32 + ac[i]);
            #pragma unroll
            for (int i = 0; i < 2; i++)
                rw[i] = *(const float4*)(W + (size_t)(n0 + wrr[i]) * 512 + kt + 32 + wcc[i]);
        }

        #pragma unroll
        for (int d = 0; d < 4; d++) {
            const int k8 = d * 8;
            unsigned ab[2][4], bb[4][2];
            #pragma unroll
            for (int mi = 0; mi < 2; mi++) {
                const int rb = wm * 32 + mi * 16;
                ab[mi][0] = Ab[rb + g][k8 + c];     ab[mi][1] = Ab[rb + g + 8][k8 + c];
                ab[mi][2] = Ab[rb + g][k8 + c + 4]; ab[mi][3] = Ab[rb + g + 8][k8 + c + 4];
            }
            #pragma unroll
            for (int ni = 0; ni < 4; ni++) {
                const int cb = wn * 32 + ni * 8;
                bb[ni][0] = Bb[cb + g][k8 + c];  bb[ni][1] = Bb[cb + g][k8 + c + 4];
            }
            #pragma unroll
            for (int mi = 0; mi < 2; mi++)
                #pragma unroll
                for (int ni = 0; ni < 4; ni++)
                    mma8(acc[mi][ni], ab[mi][0], ab[mi][1], ab[mi][2], ab[mi][3], bb[ni][0], bb[ni][1]);
        }
    }

    #pragma unroll
    for (int mi = 0; mi < 2; mi++) {
        const int r0 = m0 + wm * 32 + mi * 16 + g;
        #pragma unroll
        for (int ni = 0; ni < 4; ni++) {
            const int cc = n0 + wn * 32 + ni * 8 + c * 2;
            const float b0 = bias[cc], b1 = bias[cc + 1];
            float v[4];
            v[0] = (acc[mi][ni][0] + b0) * alpha;
            v[1] = (acc[mi][ni][1] + b1) * alpha;
            v[2] = (acc[mi][ni][2] + b0) * alpha;
            v[3] = (acc[mi][ni][3] + b1) * alpha;
            #pragma unroll
            for (int p = 0; p < 2; p++) {
                const int m = r0 + p * 8;
                #pragma unroll
                for (int q = 0; q < 2; q++) {
                    const int n = cc + q;
                    float val = v[p * 2 + q];
                    if (MODE == 0) {
                        C[(size_t)m * 512 + n] = val;
                    } else if (MODE == 1) {
                        val = __uint_as_float(f2t(val));   // pre-round for attn cp.async
                        const int b_ = m >> 11, s_ = m & 2047;
                        const int h_ = n >> 6, dk = n & 63;
                        C[(((size_t)(b_ * HH + h_)) * SS + s_) * DK + dk] = val;
                    } else {
                        // V: transposed bf16 [bh][dk][s]
                        const int b_ = m >> 11, s_ = m & 2047;
                        const int h_ = n >> 6, dk = n & 63;
                        __nv_bfloat16* Cb = (__nv_bfloat16*)C;
                        Cb[(((size_t)(b_ * HH + h_)) * DK + dk) * SS + s_] = __float2bfloat16(val);
                    }
                }
            }
        }
    }
}

// Fused Q/K/V projection: blockIdx.z selects weight/bias/output. NO min-blocks cap.
__global__ __launch_bounds__(256)
void qkv_proj_kernel(const float* __restrict__ x,
                     const float* __restrict__ Wq, const float* __restrict__ bq,
                     const float* __restrict__ Wk, const float* __restrict__ bk,
                     const float* __restrict__ Wv, const float* __restrict__ bv,
                     float qalpha) {
    extern __shared__ unsigned sh[];
    const int z = blockIdx.z;
    if (z == 0)
        proj_body<1>(x, Wq, bq, g_Q, qalpha, blockIdx.y * 128, blockIdx.x * 64, sh);
    else if (z == 1)
        proj_body<1>(x, Wk, bk, g_K, 1.0f, blockIdx.y * 128, blockIdx.x * 64, sh);
    else
        proj_body<2>(x, Wv, bv, (float*)g_Vt, 1.0f, blockIdx.y * 128, blockIdx.x * 64, sh);
}

__global__ __launch_bounds__(256)
void out_proj_kernel(const float* __restrict__ Wo, const float* __restrict__ bo,
                     float* __restrict__ out) {
    extern __shared__ unsigned sh[];
    proj_body<0>(g_attn, Wo, bo, out, 1.0f, blockIdx.y * 128, blockIdx.x * 64, sh);
}

// ---------------------------------------------------------------------------
// Flash attention: 512 threads, 256-row q-tile, 16 warps (16 rows each).
// QK^T in tf32 (k8 mma); P·V in bf16 (k16 mma) with:
//   - P converted register->register (cvt.rn.bf16x2) -- NO smem staging
//   - V pre-transposed bf16 [dk][kv] tiles via cp.async, pitch 36 words
//     (bank 4g+c -> conflict-free LDS.32 fragment loads)
// smem (words): Qs[256][68] @0 | Ks[2][64][68] @17408 | Vt[2][64][36] @26112
//               -> 30720 words = 122880 B
// ---------------------------------------------------------------------------
#define QS_OFF 0
#define KS_OFF 17408
#define VS_OFF 26112

__global__ __launch_bounds__(512)
void attn_kernel(const float* __restrict__ Q, const float* __restrict__ K,
                 const __nv_bfloat16* __restrict__ Vt, float* __restrict__ Out) {
    extern __shared__ unsigned sh[];
    unsigned (*Qs)[68] = (unsigned(*)[68])(sh + QS_OFF);

    const int tid  = threadIdx.x;
    const int lane = tid & 31;
    const int warp = tid >> 5;       // 0..15
    const int g = lane >> 2, c = lane & 3;
    const int wr = warp * 16;        // 0..240
    const int qt = blockIdx.x;       // 0..7
    const int bh = blockIdx.y;       // 0..15

    const float* Qb = Q + (size_t)bh * SS * DK + (size_t)qt * 256 * DK;
    const float* Kb = K + (size_t)bh * SS * DK;
    const __nv_bfloat16* Vb = Vt + (size_t)bh * DK * SS;   // [dk][s]

    const unsigned sbase = (unsigned)__cvta_generic_to_shared(sh);

    // K tile coords: 64x64 fp32 = 1024 16B-chunks, 2 per thread
    int rr[2], cc4[2];
    #pragma unroll
    for (int i = 0; i < 2; i++) {
        const int f = tid + i * 512;
        rr[i] = f >> 4;
        cc4[i] = (f & 15) * 4;
    }
    // V tile coords: 64 dk-rows x 8 chunks (128B bf16 row), 1 per thread
    const int vdk = tid >> 3;        // 0..63
    const int vch = tid & 7;         // 0..7

    // prologue: stage 0 K/V
    #pragma unroll
    for (int i = 0; i < 2; i++)
        CP_ASYNC16(sbase + (KS_OFF + rr[i]*68 + cc4[i]) * 4, Kb + rr[i]*64 + cc4[i]);
    CP_ASYNC16(sbase + (VS_OFF + vdk*36 + vch*4) * 4, Vb + (size_t)vdk * SS + vch * 8);
    CP_COMMIT();

    // Q tile -> tf32 smem (256x64), STS.128
    #pragma unroll
    for (int i = 0; i < 8; i++) {
        const int f = tid + i * 512;
        const int r = f >> 4, col = (f & 15) * 4;
        float4 v = *(const float4*)(Qb + r * 64 + col);
        *(uint4*)&Qs[r][col] = make_uint4(f2t(v.x), f2t(v.y), f2t(v.z), f2t(v.w));
    }

    CP_WAIT0();
    __syncthreads();

    float O[8][4] = {};
    float m0r = -1e30f, m1r = -1e30f, l0 = 0.f, l1 = 0.f;

    for (int kt = 0; kt < 32; kt++) {
        const int s = kt & 1;
        const unsigned (*Ksc)[68] = (const unsigned(*)[68])(sh + KS_OFF + s * 4352);
        const unsigned* Vsc = sh + VS_OFF + s * 2304;   // [dk][36 words]

        if (kt < 31) {
            const int s1 = s ^ 1;
            const float* Kn = Kb + (size_t)(kt + 1) * 64 * 64;
            const __nv_bfloat16* Vn = Vb + (kt + 1) * 64;
            #pragma unroll
            for (int i = 0; i < 2; i++)
                CP_ASYNC16(sbase + (KS_OFF + s1*4352 + rr[i]*68 + cc4[i]) * 4, Kn + rr[i]*64 + cc4[i]);
            CP_ASYNC16(sbase + (VS_OFF + s1*2304 + vdk*36 + vch*4) * 4, Vn + (size_t)vdk * SS + vch * 8);
            CP_COMMIT();
        }

        // S = Q K^T (tf32; log2-domain scores, Q pre-scaled by 0.125*log2e)
        float sc[8][4] = {};
        #pragma unroll
        for (int d = 0; d < 8; d++) {
            const int k8 = d * 8;
            const unsigned a0 = Qs[wr + g][k8 + c];
            const unsigned a1 = Qs[wr + g + 8][k8 + c];
            const unsigned a2 = Qs[wr + g][k8 + c + 4];
            const unsigned a3 = Qs[wr + g + 8][k8 + c + 4];
            #pragma unroll
            for (int ni = 0; ni < 8; ni++) {
                const unsigned b0 = Ksc[ni * 8 + g][k8 + c];
                const unsigned b1 = Ksc[ni * 8 + g][k8 + c + 4];
                mma8(sc[ni], a0, a1, a2, a3, b0, b1);
            }
        }

        // Online softmax (base-2)
        {
            float mx = -1e30f;
            #pragma unroll
            for (int ni = 0; ni < 8; ni++) mx = fmaxf(mx, fmaxf(sc[ni][0], sc[ni][1]));
            mx = fmaxf(mx, __shfl_xor_sync(0xffffffffu, mx, 1));
            mx = fmaxf(mx, __shfl_xor_sync(0xffffffffu, mx, 2));
            const float mn = fmaxf(m0r, mx);
            const float corr = exp2f(m0r - mn);
            m0r = mn;
            float s_ = 0.f;
            #pragma unroll
            for (int ni = 0; ni < 8; ni++) {
                sc[ni][0] = exp2f(sc[ni][0] - mn);
                sc[ni][1] = exp2f(sc[ni][1] - mn);
                s_ += sc[ni][0] + sc[ni][1];
            }
            s_ += __shfl_xor_sync(0xffffffffu, s_, 1);
            s_ += __shfl_xor_sync(0xffffffffu, s_, 2);
            l0 = l0 * corr + s_;
            #pragma unroll
            for (int ni = 0; ni < 8; ni++) { O[ni][0] *= corr; O[ni][1] *= corr; }
        }
        {
            float mx = -1e30f;
            #pragma unroll
            for (int ni = 0; ni < 8; ni++) mx = fmaxf(mx, fmaxf(sc[ni][2], sc[ni][3]));
            mx = fmaxf(mx, __shfl_xor_sync(0xffffffffu, mx, 1));
            mx = fmaxf(mx, __shfl_xor_sync(0xffffffffu, mx, 2));
            const float mn = fmaxf(m1r, mx);
            const float corr = exp2f(m1r - mn);
            m1r = mn;
            float s_ = 0.f;
            #pragma unroll
            for (int ni = 0; ni < 8; ni++) {
                sc[ni][2] = exp2f(sc[ni][2] - mn);
                sc[ni][3] = exp2f(sc[ni][3] - mn);
                s_ += sc[ni][2] + sc[ni][3];
            }
            s_ += __shfl_xor_sync(0xffffffffu, s_, 1);
            s_ += __shfl_xor_sync(0xffffffffu, s_, 2);
            l1 = l1 * corr + s_;
            #pragma unroll
            for (int ni = 0; ni < 8; ni++) { O[ni][2] *= corr; O[ni][3] *= corr; }
        }

        // O += P @ V  (bf16 k16 mma; P packed straight from score registers)
        #pragma unroll
        for (int kb = 0; kb < 4; kb++) {
            const unsigned pa0 = packbf(sc[2*kb][0],   sc[2*kb][1]);     // row g,   k 0..7
            const unsigned pa1 = packbf(sc[2*kb][2],   sc[2*kb][3]);     // row g+8, k 0..7
            const unsigned pa2 = packbf(sc[2*kb+1][0], sc[2*kb+1][1]);   // row g,   k 8..15
            const unsigned pa3 = packbf(sc[2*kb+1][2], sc[2*kb+1][3]);   // row g+8, k 8..15
            #pragma unroll
            for (int ni = 0; ni < 8; ni++) {
                const unsigned b0 = Vsc[(ni * 8 + g) * 36 + 8 * kb + c];
                const unsigned b1 = Vsc[(ni * 8 + g) * 36 + 8 * kb + 4 + c];
                mma16(O[ni], pa0, pa1, pa2, pa3, b0, b1);
            }
        }

        CP_WAIT0();
        __syncthreads();
    }

    // Normalize + write [B,S,D]
    const int b_ = bh >> 3, h_ = bh & 7;
    const float inv0 = 1.0f / l0, inv1 = 1.0f / l1;
    const int s0 = qt * 256 + wr + g;
    float* o0 = Out + ((size_t)(b_ * SS + s0)) * DD + h_ * 64;
    float* o1 = o0 + 8 * DD;
    #pragma unroll
    for (int ni = 0; ni < 8; ni++) {
        const int cc = ni * 8 + c * 2;
        o0[cc]     = O[ni][0] * inv0;
        o0[cc + 1] = O[ni][1] * inv0;
        o1[cc]     = O[ni][2] * inv1;
        o1[cc + 1] = O[ni][3] * inv1;
    }
}

// ---------------------------------------------------------------------------

extern "C" void kernel_launch(void* const* d_in, const int* in_sizes, int n_in,
                              void* d_out, int out_size) {
    const float* x  = (const float*)d_in[0];
    const float* Wq = (const float*)d_in[1];
    const float* bq = (const float*)d_in[2];
    const float* Wk = (const float*)d_in[3];
    const float* bk = (const float*)d_in[4];
    const float* Wv = (const float*)d_in[5];
    const float* bv = (const float*)d_in[6];
    const float* Wo = (const float*)d_in[7];
    const float* bo = (const float*)d_in[8];
    float* out = (float*)d_out;

    float *Q, *K, *attn;
    __nv_bfloat16* Vt;
    cudaGetSymbolAddress((void**)&Q, g_Q);
    cudaGetSymbolAddress((void**)&K, g_K);
    cudaGetSymbolAddress((void**)&Vt, g_Vt);
    cudaGetSymbolAddress((void**)&attn, g_attn);

    const int proj_smem = (128 * 36 + 64 * 36) * 4;   // 27648 B
    const int attn_smem = 30720 * 4;                   // 122880 B
    cudaFuncSetAttribute(qkv_proj_kernel, cudaFuncAttributeMaxDynamicSharedMemorySize, proj_smem);
    cudaFuncSetAttribute(out_proj_kernel, cudaFuncAttributeMaxDynamicSharedMemorySize, proj_smem);
    cudaFuncSetAttribute(attn_kernel,     cudaFuncAttributeMaxDynamicSharedMemorySize, attn_smem);

    // Fused QKV; Q gets 1/sqrt(64) * log2(e) folded in (exp2 softmax)
    const float qalpha = 0.125f * 1.4426950408889634f;
    qkv_proj_kernel<<<dim3(8, 32, 3), 256, proj_smem>>>(x, Wq, bq, Wk, bk, Wv, bv, qalpha);

    attn_kernel<<<dim3(8, 16), 512, attn_smem>>>(Q, K, Vt, attn);

    out_proj_kernel<<<dim3(8, 32), 256, proj_smem>>>(Wo, bo, out);
}

// round 14
// speedup vs baseline: 1.8046x; 1.0238x over previous
#include <cuda_runtime.h>
#include <cuda_bf16.h>
#include <math.h>

#define BB 2
#define SS 2048
#define DD 512
#define HH 8
#define DK 64
#define M_TOTAL (BB*SS)   // 4096

// Scratch (allocation-free)
__device__ float g_Q[BB*HH*SS*DK];
__device__ float g_K[BB*HH*SS*DK];
__device__ __nv_bfloat16 g_Vt[BB*HH*DK*SS];   // transposed: [bh][dk][s]
__device__ float g_attn[BB*SS*DD];

// ---------------------------------------------------------------------------
__device__ __forceinline__ unsigned f2t(float x) {
    unsigned r;
    asm("cvt.rna.tf32.f32 %0, %1;" : "=r"(r) : "f"(x));
    return r;
}

__device__ __forceinline__ unsigned packbf(float lo, float hi) {
    unsigned r;
    asm("cvt.rn.bf16x2.f32 %0, %1, %2;" : "=r"(r) : "f"(hi), "f"(lo));
    return r;
}

__device__ __forceinline__ void mma8(float* c,
                                     unsigned a0, unsigned a1, unsigned a2, unsigned a3,
                                     unsigned b0, unsigned b1) {
    asm volatile(
        "mma.sync.aligned.m16n8k8.row.col.f32.tf32.tf32.f32 "
        "{%0,%1,%2,%3}, {%4,%5,%6,%7}, {%8,%9}, {%0,%1,%2,%3};"
        : "+f"(c[0]), "+f"(c[1]), "+f"(c[2]), "+f"(c[3])
        : "r"(a0), "r"(a1), "r"(a2), "r"(a3), "r"(b0), "r"(b1));
}

__device__ __forceinline__ void mma16(float* c,
                                      unsigned a0, unsigned a1, unsigned a2, unsigned a3,
                                      unsigned b0, unsigned b1) {
    asm volatile(
        "mma.sync.aligned.m16n8k16.row.col.f32.bf16.bf16.f32 "
        "{%0,%1,%2,%3}, {%4,%5,%6,%7}, {%8,%9}, {%0,%1,%2,%3};"
        : "+f"(c[0]), "+f"(c[1]), "+f"(c[2]), "+f"(c[3])
        : "r"(a0), "r"(a1), "r"(a2), "r"(a3), "r"(b0), "r"(b1));
}

#define CP_ASYNC16(smem_u32, gptr) \
    asm volatile("cp.async.cg.shared.global [%0], [%1], 16;" :: "r"(smem_u32), "l"(gptr))
#define CP_COMMIT()  asm volatile("cp.async.commit_group;" ::: "memory")
#define CP_WAIT0()   asm volatile("cp.async.wait_group 0;" ::: "memory")

// ---------------------------------------------------------------------------
// Single-pass TF32 GEMM body, cp.async double-buffered A/W staging (raw fp32),
// f2t applied at fragment-load time (bit-identical to store-time rounding).
// C = (A @ W^T + bias) * alpha. Block 128x64, BK=32, 8 warps (4x2), pitch 36.
// Stage layout (words): A rows [0..128), W rows [128..192); stage stride 6912.
// MODE 0: row-major [M,N] fp32.
// MODE 1: head-split [B,H,S,DK] fp32 + tf32-RNA pre-round.
// MODE 2: head-split TRANSPOSED [B,H,DK,S] bf16 (for attn V).
// ---------------------------------------------------------------------------
#define PSTG 6912   // words per stage: 192 rows * 36

template<int MODE>
__device__ __forceinline__
void proj_body(const float* __restrict__ A, const float* __restrict__ W,
               const float* __restrict__ bias, float* __restrict__ C,
               float alpha, int m0, int n0, unsigned* sh) {
    const int tid  = threadIdx.x;
    const int lane = tid & 31;
    const int warp = tid >> 5;
    const int g = lane >> 2, c = lane & 3;
    const int wm = warp & 3, wn = warp >> 2;
    const unsigned sbase = (unsigned)__cvta_generic_to_shared(sh);

    int ar[4], ac[4], wrr[2], wcc[2];
    #pragma unroll
    for (int i = 0; i < 4; i++) {
        const int f = tid + i * 256;
        ar[i] = f >> 3; ac[i] = (f & 7) * 4;
    }
    #pragma unroll
    for (int i = 0; i < 2; i++) {
        const int f = tid + i * 256;
        wrr[i] = f >> 3; wcc[i] = (f & 7) * 4;
    }

    // prologue: fill stage 0
    #pragma unroll
    for (int i = 0; i < 4; i++)
        CP_ASYNC16(sbase + (ar[i]*36 + ac[i]) * 4,
                   A + (size_t)(m0 + ar[i]) * 512 + ac[i]);
    #pragma unroll
    for (int i = 0; i < 2; i++)
        CP_ASYNC16(sbase + ((128 + wrr[i])*36 + wcc[i]) * 4,
                   W + (size_t)(n0 + wrr[i]) * 512 + wcc[i]);
    CP_COMMIT();
    CP_WAIT0();
    __syncthreads();

    float acc[2][4][4] = {};

    for (int kt = 0; kt < 16; kt++) {
        const int s = kt & 1;
        const float* St = (const float*)(sh + s * PSTG);

        // fill next stage (overlaps compute)
        if (kt < 15) {
            const int s1 = s ^ 1;
            const int ko = (kt + 1) * 32;
            #pragma unroll
            for (int i = 0; i < 4; i++)
                CP_ASYNC16(sbase + (s1*PSTG + ar[i]*36 + ac[i]) * 4,
                           A + (size_t)(m0 + ar[i]) * 512 + ko + ac[i]);
            #pragma unroll
            for (int i = 0; i < 2; i++)
                CP_ASYNC16(sbase + (s1*PSTG + (128 + wrr[i])*36 + wcc[i]) * 4,
                           W + (size_t)(n0 + wrr[i]) * 512 + ko + wcc[i]);
            CP_COMMIT();
        }

        #pragma unroll
        for (int d = 0; d < 4; d++) {
            const int k8 = d * 8;
            unsigned ab[2][4], bb[4][2];
            #pragma unroll
            for (int mi = 0; mi < 2; mi++) {
                const int rb = wm * 32 + mi * 16;
                ab[mi][0] = f2t(St[(rb + g) * 36 + k8 + c]);
                ab[mi][1] = f2t(St[(rb + g + 8) * 36 + k8 + c]);
                ab[mi][2] = f2t(St[(rb + g) * 36 + k8 + c + 4]);
                ab[mi][3] = f2t(St[(rb + g + 8) * 36 + k8 + c + 4]);
            }
            #pragma unroll
            for (int ni = 0; ni < 4; ni++) {
                const int cb = 128 + wn * 32 + ni * 8;
                bb[ni][0] = f2t(St[(cb + g) * 36 + k8 + c]);
                bb[ni][1] = f2t(St[(cb + g) * 36 + k8 + c + 4]);
            }
            #pragma unroll
            for (int mi = 0; mi < 2; mi++)
                #pragma unroll
                for (int ni = 0; ni < 4; ni++)
                    mma8(acc[mi][ni], ab[mi][0], ab[mi][1], ab[mi][2], ab[mi][3], bb[ni][0], bb[ni][1]);
        }

        CP_WAIT0();
        __syncthreads();
    }

    #pragma unroll
    for (int mi = 0; mi < 2; mi++) {
        const int r0 = m0 + wm * 32 + mi * 16 + g;
        #pragma unroll
        for (int ni = 0; ni < 4; ni++) {
            const int cc = n0 + wn * 32 + ni * 8 + c * 2;
            const float b0 = bias[cc], b1 = bias[cc + 1];
            float v[4];
            v[0] = (acc[mi][ni][0] + b0) * alpha;
            v[1] = (acc[mi][ni][1] + b1) * alpha;
            v[2] = (acc[mi][ni][2] + b0) * alpha;
            v[3] = (acc[mi][ni][3] + b1) * alpha;
            #pragma unroll
            for (int p = 0; p < 2; p++) {
                const int m = r0 + p * 8;
                #pragma unroll
                for (int q = 0; q < 2; q++) {
                    const int n = cc + q;
                    float val = v[p * 2 + q];
                    if (MODE == 0) {
                        C[(size_t)m * 512 + n] = val;
                    } else if (MODE == 1) {
                        val = __uint_as_float(f2t(val));   // pre-round for attn cp.async
                        const int b_ = m >> 11, s_ = m & 2047;
                        const int h_ = n >> 6, dk = n & 63;
                        C[(((size_t)(b_ * HH + h_)) * SS + s_) * DK + dk] = val;
                    } else {
                        // V: transposed bf16 [bh][dk][s]
                        const int b_ = m >> 11, s_ = m & 2047;
                        const int h_ = n >> 6, dk = n & 63;
                        __nv_bfloat16* Cb = (__nv_bfloat16*)C;
                        Cb[(((size_t)(b_ * HH + h_)) * DK + dk) * SS + s_] = __float2bfloat16(val);
                    }
                }
            }
        }
    }
}

// Fused Q/K/V projection: blockIdx.z selects weight/bias/output. NO min-blocks cap.
__global__ __launch_bounds__(256)
void qkv_proj_kernel(const float* __restrict__ x,
                     const float* __restrict__ Wq, const float* __restrict__ bq,
                     const float* __restrict__ Wk, const float* __restrict__ bk,
                     const float* __restrict__ Wv, const float* __restrict__ bv,
                     float qalpha) {
    extern __shared__ unsigned sh[];
    const int z = blockIdx.z;
    if (z == 0)
        proj_body<1>(x, Wq, bq, g_Q, qalpha, blockIdx.y * 128, blockIdx.x * 64, sh);
    else if (z == 1)
        proj_body<1>(x, Wk, bk, g_K, 1.0f, blockIdx.y * 128, blockIdx.x * 64, sh);
    else
        proj_body<2>(x, Wv, bv, (float*)g_Vt, 1.0f, blockIdx.y * 128, blockIdx.x * 64, sh);
}

__global__ __launch_bounds__(256)
void out_proj_kernel(const float* __restrict__ Wo, const float* __restrict__ bo,
                     float* __restrict__ out) {
    extern __shared__ unsigned sh[];
    proj_body<0>(g_attn, Wo, bo, out, 1.0f, blockIdx.y * 128, blockIdx.x * 64, sh);
}

// ---------------------------------------------------------------------------
// Flash attention: unchanged from R12 (verified). 512 threads, 256-row q-tile,
// 16 warps; QK^T tf32, P·V bf16 with register-packed P and pre-transposed V.
// smem (words): Qs[256][68] @0 | Ks[2][64][68] @17408 | Vt[2][64][36] @26112
//               -> 30720 words = 122880 B
// ---------------------------------------------------------------------------
#define QS_OFF 0
#define KS_OFF 17408
#define VS_OFF 26112

__global__ __launch_bounds__(512)
void attn_kernel(const float* __restrict__ Q, const float* __restrict__ K,
                 const __nv_bfloat16* __restrict__ Vt, float* __restrict__ Out) {
    extern __shared__ unsigned sh[];
    unsigned (*Qs)[68] = (unsigned(*)[68])(sh + QS_OFF);

    const int tid  = threadIdx.x;
    const int lane = tid & 31;
    const int warp = tid >> 5;       // 0..15
    const int g = lane >> 2, c = lane & 3;
    const int wr = warp * 16;        // 0..240
    const int qt = blockIdx.x;       // 0..7
    const int bh = blockIdx.y;       // 0..15

    const float* Qb = Q + (size_t)bh * SS * DK + (size_t)qt * 256 * DK;
    const float* Kb = K + (size_t)bh * SS * DK;
    const __nv_bfloat16* Vb = Vt + (size_t)bh * DK * SS;   // [dk][s]

    const unsigned sbase = (unsigned)__cvta_generic_to_shared(sh);

    int rr[2], cc4[2];
    #pragma unroll
    for (int i = 0; i < 2; i++) {
        const int f = tid + i * 512;
        rr[i] = f >> 4;
        cc4[i] = (f & 15) * 4;
    }
    const int vdk = tid >> 3;        // 0..63
    const int vch = tid & 7;         // 0..7

    // prologue: stage 0 K/V
    #pragma unroll
    for (int i = 0; i < 2; i++)
        CP_ASYNC16(sbase + (KS_OFF + rr[i]*68 + cc4[i]) * 4, Kb + rr[i]*64 + cc4[i]);
    CP_ASYNC16(sbase + (VS_OFF + vdk*36 + vch*4) * 4, Vb + (size_t)vdk * SS + vch * 8);
    CP_COMMIT();

    // Q tile -> tf32 smem (256x64), STS.128
    #pragma unroll
    for (int i = 0; i < 8; i++) {
        const int f = tid + i * 512;
        const int r = f >> 4, col = (f & 15) * 4;
        float4 v = *(const float4*)(Qb + r * 64 + col);
        *(uint4*)&Qs[r][col] = make_uint4(f2t(v.x), f2t(v.y), f2t(v.z), f2t(v.w));
    }

    CP_WAIT0();
    __syncthreads();

    float O[8][4] = {};
    float m0r = -1e30f, m1r = -1e30f, l0 = 0.f, l1 = 0.f;

    for (int kt = 0; kt < 32; kt++) {
        const int s = kt & 1;
        const unsigned (*Ksc)[68] = (const unsigned(*)[68])(sh + KS_OFF + s * 4352);
        const unsigned* Vsc = sh + VS_OFF + s * 2304;   // [dk][36 words]

        if (kt < 31) {
            const int s1 = s ^ 1;
            const float* Kn = Kb + (size_t)(kt + 1) * 64 * 64;
            const __nv_bfloat16* Vn = Vb + (kt + 1) * 64;
            #pragma unroll
            for (int i = 0; i < 2; i++)
                CP_ASYNC16(sbase + (KS_OFF + s1*4352 + rr[i]*68 + cc4[i]) * 4, Kn + rr[i]*64 + cc4[i]);
            CP_ASYNC16(sbase + (VS_OFF + s1*2304 + vdk*36 + vch*4) * 4, Vn + (size_t)vdk * SS + vch * 8);
            CP_COMMIT();
        }

        // S = Q K^T (tf32; log2-domain scores, Q pre-scaled by 0.125*log2e)
        float sc[8][4] = {};
        #pragma unroll
        for (int d = 0; d < 8; d++) {
            const int k8 = d * 8;
            const unsigned a0 = Qs[wr + g][k8 + c];
            const unsigned a1 = Qs[wr + g + 8][k8 + c];
            const unsigned a2 = Qs[wr + g][k8 + c + 4];
            const unsigned a3 = Qs[wr + g + 8][k8 + c + 4];
            #pragma unroll
            for (int ni = 0; ni < 8; ni++) {
                const unsigned b0 = Ksc[ni * 8 + g][k8 + c];
                const unsigned b1 = Ksc[ni * 8 + g][k8 + c + 4];
                mma8(sc[ni], a0, a1, a2, a3, b0, b1);
            }
        }

        // Online softmax (base-2)
        {
            float mx = -1e30f;
            #pragma unroll
            for (int ni = 0; ni < 8; ni++) mx = fmaxf(mx, fmaxf(sc[ni][0], sc[ni][1]));
            mx = fmaxf(mx, __shfl_xor_sync(0xffffffffu, mx, 1));
            mx = fmaxf(mx, __shfl_xor_sync(0xffffffffu, mx, 2));
            const float mn = fmaxf(m0r, mx);
            const float corr = exp2f(m0r - mn);
            m0r = mn;
            float s_ = 0.f;
            #pragma unroll
            for (int ni = 0; ni < 8; ni++) {
                sc[ni][0] = exp2f(sc[ni][0] - mn);
                sc[ni][1] = exp2f(sc[ni][1] - mn);
                s_ += sc[ni][0] + sc[ni][1];
            }
            s_ += __shfl_xor_sync(0xffffffffu, s_, 1);
            s_ += __shfl_xor_sync(0xffffffffu, s_, 2);
            l0 = l0 * corr + s_;
            #pragma unroll
            for (int ni = 0; ni < 8; ni++) { O[ni][0] *= corr; O[ni][1] *= corr; }
        }
        {
            float mx = -1e30f;
            #pragma unroll
            for (int ni = 0; ni < 8; ni++) mx = fmaxf(mx, fmaxf(sc[ni][2], sc[ni][3]));
            mx = fmaxf(mx, __shfl_xor_sync(0xffffffffu, mx, 1));
            mx = fmaxf(mx, __shfl_xor_sync(0xffffffffu, mx, 2));
            const float mn = fmaxf(m1r, mx);
            const float corr = exp2f(m1r - mn);
            m1r = mn;
            float s_ = 0.f;
            #pragma unroll
            for (int ni = 0; ni < 8; ni++) {
                sc[ni][2] = exp2f(sc[ni][2] - mn);
                sc[ni][3] = exp2f(sc[ni][3] - mn);
                s_ += sc[ni][2] + sc[ni][3];
            }
            s_ += __shfl_xor_sync(0xffffffffu, s_, 1);
            s_ += __shfl_xor_sync(0xffffffffu, s_, 2);
            l1 = l1 * corr + s_;
            #pragma unroll
            for (int ni = 0; ni < 8; ni++) { O[ni][2] *= corr; O[ni][3] *= corr; }
        }

        // O += P @ V  (bf16 k16 mma; P packed straight from score registers)
        #pragma unroll
        for (int kb = 0; kb < 4; kb++) {
            const unsigned pa0 = packbf(sc[2*kb][0],   sc[2*kb][1]);
            const unsigned pa1 = packbf(sc[2*kb][2],   sc[2*kb][3]);
            const unsigned pa2 = packbf(sc[2*kb+1][0], sc[2*kb+1][1]);
            const unsigned pa3 = packbf(sc[2*kb+1][2], sc[2*kb+1][3]);
            #pragma unroll
            for (int ni = 0; ni < 8; ni++) {
                const unsigned b0 = Vsc[(ni * 8 + g) * 36 + 8 * kb + c];
                const unsigned b1 = Vsc[(ni * 8 + g) * 36 + 8 * kb + 4 + c];
                mma16(O[ni], pa0, pa1, pa2, pa3, b0, b1);
            }
        }

        CP_WAIT0();
        __syncthreads();
    }

    // Normalize + write [B,S,D]
    const int b_ = bh >> 3, h_ = bh & 7;
    const float inv0 = 1.0f / l0, inv1 = 1.0f / l1;
    const int s0 = qt * 256 + wr + g;
    float* o0 = Out + ((size_t)(b_ * SS + s0)) * DD + h_ * 64;
    float* o1 = o0 + 8 * DD;
    #pragma unroll
    for (int ni = 0; ni < 8; ni++) {
        const int cc = ni * 8 + c * 2;
        o0[cc]     = O[ni][0] * inv0;
        o0[cc + 1] = O[ni][1] * inv0;
        o1[cc]     = O[ni][2] * inv1;
        o1[cc + 1] = O[ni][3] * inv1;
    }
}

// ---------------------------------------------------------------------------

extern "C" void kernel_launch(void* const* d_in, const int* in_sizes, int n_in,
                              void* d_out, int out_size) {
    const float* x  = (const float*)d_in[0];
    const float* Wq = (const float*)d_in[1];
    const float* bq = (const float*)d_in[2];
    const float* Wk = (const float*)d_in[3];
    const float* bk = (const float*)d_in[4];
    const float* Wv = (const float*)d_in[5];
    const float* bv = (const float*)d_in[6];
    const float* Wo = (const float*)d_in[7];
    const float* bo = (const float*)d_in[8];
    float* out = (float*)d_out;

    float *Q, *K, *attn;
    __nv_bfloat16* Vt;
    cudaGetSymbolAddress((void**)&Q, g_Q);
    cudaGetSymbolAddress((void**)&K, g_K);
    cudaGetSymbolAddress((void**)&Vt, g_Vt);
    cudaGetSymbolAddress((void**)&attn, g_attn);

    const int proj_smem = 2 * PSTG * 4;   // 55296 B (2-stage raw fp32 staging)
    const int attn_smem = 30720 * 4;      // 122880 B
    cudaFuncSetAttribute(qkv_proj_kernel, cudaFuncAttributeMaxDynamicSharedMemorySize, proj_smem);
    cudaFuncSetAttribute(out_proj_kernel, cudaFuncAttributeMaxDynamicSharedMemorySize, proj_smem);
    cudaFuncSetAttribute(attn_kernel,     cudaFuncAttributeMaxDynamicSharedMemorySize, attn_smem);

    // Fused QKV; Q gets 1/sqrt(64) * log2(e) folded in (exp2 softmax)
    const float qalpha = 0.125f * 1.4426950408889634f;
    qkv_proj_kernel<<<dim3(8, 32, 3), 256, proj_smem>>>(x, Wq, bq, Wk, bk, Wv, bv, qalpha);

    attn_kernel<<<dim3(8, 16), 512, attn_smem>>>(Q, K, Vt, attn);

    out_proj_kernel<<<dim3(8, 32), 256, proj_smem>>>(Wo, bo, out);
}

// round 16
// speedup vs baseline: 1.8703x; 1.0364x over previous
#include <cuda_runtime.h>
#include <cuda_bf16.h>
#include <math.h>

#define BB 2
#define SS 2048
#define DD 512
#define HH 8
#define DK 64
#define M_TOTAL (BB*SS)   // 4096

// Scratch (allocation-free)
__device__ float g_Q[BB*HH*SS*DK];
__device__ float g_K[BB*HH*SS*DK];
__device__ __nv_bfloat16 g_Vt[BB*HH*DK*SS];   // transposed: [bh][dk][s]
__device__ float g_attn[BB*SS*DD];

// ---------------------------------------------------------------------------
__device__ __forceinline__ unsigned f2t(float x) {
    unsigned r;
    asm("cvt.rna.tf32.f32 %0, %1;" : "=r"(r) : "f"(x));
    return r;
}

__device__ __forceinline__ unsigned packbf(float lo, float hi) {
    unsigned r;
    asm("cvt.rn.bf16x2.f32 %0, %1, %2;" : "=r"(r) : "f"(hi), "f"(lo));
    return r;
}

__device__ __forceinline__ void mma8(float* c,
                                     unsigned a0, unsigned a1, unsigned a2, unsigned a3,
                                     unsigned b0, unsigned b1) {
    asm volatile(
        "mma.sync.aligned.m16n8k8.row.col.f32.tf32.tf32.f32 "
        "{%0,%1,%2,%3}, {%4,%5,%6,%7}, {%8,%9}, {%0,%1,%2,%3};"
        : "+f"(c[0]), "+f"(c[1]), "+f"(c[2]), "+f"(c[3])
        : "r"(a0), "r"(a1), "r"(a2), "r"(a3), "r"(b0), "r"(b1));
}

__device__ __forceinline__ void mma16(float* c,
                                      unsigned a0, unsigned a1, unsigned a2, unsigned a3,
                                      unsigned b0, unsigned b1) {
    asm volatile(
        "mma.sync.aligned.m16n8k16.row.col.f32.bf16.bf16.f32 "
        "{%0,%1,%2,%3}, {%4,%5,%6,%7}, {%8,%9}, {%0,%1,%2,%3};"
        : "+f"(c[0]), "+f"(c[1]), "+f"(c[2]), "+f"(c[3])
        : "r"(a0), "r"(a1), "r"(a2), "r"(a3), "r"(b0), "r"(b1));
}

#define CP_ASYNC16(smem_u32, gptr) \
    asm volatile("cp.async.cg.shared.global [%0], [%1], 16;" :: "r"(smem_u32), "l"(gptr))
#define CP_COMMIT()  asm volatile("cp.async.commit_group;" ::: "memory")
#define CP_WAIT0()   asm volatile("cp.async.wait_group 0;" ::: "memory")

// ---------------------------------------------------------------------------
// Single-pass TF32 GEMM body (unchanged from R13, verified).
// cp.async double-buffered A/W staging (raw fp32), f2t at fragment-load time.
// C = (A @ W^T + bias) * alpha. Block 128x64, BK=32, 8 warps (4x2), pitch 36.
// MODE 0: row-major [M,N] fp32.
// MODE 1: head-split [B,H,S,DK] fp32 + tf32-RNA pre-round.
// MODE 2: head-split TRANSPOSED [B,H,DK,S] bf16 (for attn V).
// ---------------------------------------------------------------------------
#define PSTG 6912   // words per stage: 192 rows * 36

template<int MODE>
__device__ __forceinline__
void proj_body(const float* __restrict__ A, const float* __restrict__ W,
               const float* __restrict__ bias, float* __restrict__ C,
               float alpha, int m0, int n0, unsigned* sh) {
    const int tid  = threadIdx.x;
    const int lane = tid & 31;
    const int warp = tid >> 5;
    const int g = lane >> 2, c = lane & 3;
    const int wm = warp & 3, wn = warp >> 2;
    const unsigned sbase = (unsigned)__cvta_generic_to_shared(sh);

    int ar[4], ac[4], wrr[2], wcc[2];
    #pragma unroll
    for (int i = 0; i < 4; i++) {
        const int f = tid + i * 256;
        ar[i] = f >> 3; ac[i] = (f & 7) * 4;
    }
    #pragma unroll
    for (int i = 0; i < 2; i++) {
        const int f = tid + i * 256;
        wrr[i] = f >> 3; wcc[i] = (f & 7) * 4;
    }

    // prologue: fill stage 0
    #pragma unroll
    for (int i = 0; i < 4; i++)
        CP_ASYNC16(sbase + (ar[i]*36 + ac[i]) * 4,
                   A + (size_t)(m0 + ar[i]) * 512 + ac[i]);
    #pragma unroll
    for (int i = 0; i < 2; i++)
        CP_ASYNC16(sbase + ((128 + wrr[i])*36 + wcc[i]) * 4,
                   W + (size_t)(n0 + wrr[i]) * 512 + wcc[i]);
    CP_COMMIT();
    CP_WAIT0();
    __syncthreads();

    float acc[2][4][4] = {};

    for (int kt = 0; kt < 16; kt++) {
        const int s = kt & 1;
        const float* St = (const float*)(sh + s * PSTG);

        if (kt < 15) {
            const int s1 = s ^ 1;
            const int ko = (kt + 1) * 32;
            #pragma unroll
            for (int i = 0; i < 4; i++)
                CP_ASYNC16(sbase + (s1*PSTG + ar[i]*36 + ac[i]) * 4,
                           A + (size_t)(m0 + ar[i]) * 512 + ko + ac[i]);
            #pragma unroll
            for (int i = 0; i < 2; i++)
                CP_ASYNC16(sbase + (s1*PSTG + (128 + wrr[i])*36 + wcc[i]) * 4,
                           W + (size_t)(n0 + wrr[i]) * 512 + ko + wcc[i]);
            CP_COMMIT();
        }

        #pragma unroll
        for (int d = 0; d < 4; d++) {
            const int k8 = d * 8;
            unsigned ab[2][4], bb[4][2];
            #pragma unroll
            for (int mi = 0; mi < 2; mi++) {
                const int rb = wm * 32 + mi * 16;
                ab[mi][0] = f2t(St[(rb + g) * 36 + k8 + c]);
                ab[mi][1] = f2t(St[(rb + g + 8) * 36 + k8 + c]);
                ab[mi][2] = f2t(St[(rb + g) * 36 + k8 + c + 4]);
                ab[mi][3] = f2t(St[(rb + g + 8) * 36 + k8 + c + 4]);
            }
            #pragma unroll
            for (int ni = 0; ni < 4; ni++) {
                const int cb = 128 + wn * 32 + ni * 8;
                bb[ni][0] = f2t(St[(cb + g) * 36 + k8 + c]);
                bb[ni][1] = f2t(St[(cb + g) * 36 + k8 + c + 4]);
            }
            #pragma unroll
            for (int mi = 0; mi < 2; mi++)
                #pragma unroll
                for (int ni = 0; ni < 4; ni++)
                    mma8(acc[mi][ni], ab[mi][0], ab[mi][1], ab[mi][2], ab[mi][3], bb[ni][0], bb[ni][1]);
        }

        CP_WAIT0();
        __syncthreads();
    }

    #pragma unroll
    for (int mi = 0; mi < 2; mi++) {
        const int r0 = m0 + wm * 32 + mi * 16 + g;
        #pragma unroll
        for (int ni = 0; ni < 4; ni++) {
            const int cc = n0 + wn * 32 + ni * 8 + c * 2;
            const float b0 = bias[cc], b1 = bias[cc + 1];
            float v[4];
            v[0] = (acc[mi][ni][0] + b0) * alpha;
            v[1] = (acc[mi][ni][1] + b1) * alpha;
            v[2] = (acc[mi][ni][2] + b0) * alpha;
            v[3] = (acc[mi][ni][3] + b1) * alpha;
            #pragma unroll
            for (int p = 0; p < 2; p++) {
                const int m = r0 + p * 8;
                #pragma unroll
                for (int q = 0; q < 2; q++) {
                    const int n = cc + q;
                    float val = v[p * 2 + q];
                    if (MODE == 0) {
                        C[(size_t)m * 512 + n] = val;
                    } else if (MODE == 1) {
                        val = __uint_as_float(f2t(val));   // pre-round for attn
                        const int b_ = m >> 11, s_ = m & 2047;
                        const int h_ = n >> 6, dk = n & 63;
                        C[(((size_t)(b_ * HH + h_)) * SS + s_) * DK + dk] = val;
                    } else {
                        const int b_ = m >> 11, s_ = m & 2047;
                        const int h_ = n >> 6, dk = n & 63;
                        __nv_bfloat16* Cb = (__nv_bfloat16*)C;
                        Cb[(((size_t)(b_ * HH + h_)) * DK + dk) * SS + s_] = __float2bfloat16(val);
                    }
                }
            }
        }
    }
}

// Fused Q/K/V projection: blockIdx.z selects weight/bias/output. NO min-blocks cap.
__global__ __launch_bounds__(256)
void qkv_proj_kernel(const float* __restrict__ x,
                     const float* __restrict__ Wq, const float* __restrict__ bq,
                     const float* __restrict__ Wk, const float* __restrict__ bk,
                     const float* __restrict__ Wv, const float* __restrict__ bv,
                     float qalpha) {
    extern __shared__ unsigned sh[];
    const int z = blockIdx.z;
    if (z == 0)
        proj_body<1>(x, Wq, bq, g_Q, qalpha, blockIdx.y * 128, blockIdx.x * 64, sh);
    else if (z == 1)
        proj_body<1>(x, Wk, bk, g_K, 1.0f, blockIdx.y * 128, blockIdx.x * 64, sh);
    else
        proj_body<2>(x, Wv, bv, (float*)g_Vt, 1.0f, blockIdx.y * 128, blockIdx.x * 64, sh);
}

__global__ __launch_bounds__(256)
void out_proj_kernel(const float* __restrict__ Wo, const float* __restrict__ bo,
                     float* __restrict__ out) {
    extern __shared__ unsigned sh[];
    proj_body<0>(g_attn, Wo, bo, out, 1.0f, blockIdx.y * 128, blockIdx.x * 64, sh);
}

// ---------------------------------------------------------------------------
// Flash attention: 512 threads, 256-row q-tile, 16 warps (16 rows each).
// NEW: Q fragments live in REGISTERS for the whole kernel (loaded once from
// global in the prologue) -- no Qs smem, no per-iteration Q LDS.
// QK^T tf32; P·V bf16 with register-packed P and pre-transposed V (unchanged).
// smem (words): Ks[2][64][68] @0 | Vt[2][64][36] @8704 -> 13312 words = 53248 B
// ---------------------------------------------------------------------------
#define KS_OFF 0
#define VS_OFF 8704

__global__ __launch_bounds__(512)
void attn_kernel(const float* __restrict__ Q, const float* __restrict__ K,
                 const __nv_bfloat16* __restrict__ Vt, float* __restrict__ Out) {
    extern __shared__ unsigned sh[];

    const int tid  = threadIdx.x;
    const int lane = tid & 31;
    const int warp = tid >> 5;       // 0..15
    const int g = lane >> 2, c = lane & 3;
    const int wr = warp * 16;        // 0..240
    const int qt = blockIdx.x;       // 0..7
    const int bh = blockIdx.y;       // 0..15

    const float* Qb = Q + (size_t)bh * SS * DK + (size_t)qt * 256 * DK;
    const float* Kb = K + (size_t)bh * SS * DK;
    const __nv_bfloat16* Vb = Vt + (size_t)bh * DK * SS;   // [dk][s]

    const unsigned sbase = (unsigned)__cvta_generic_to_shared(sh);

    int rr[2], cc4[2];
    #pragma unroll
    for (int i = 0; i < 2; i++) {
        const int f = tid + i * 512;
        rr[i] = f >> 4;
        cc4[i] = (f & 15) * 4;
    }
    const int vdk = tid >> 3;        // 0..63
    const int vch = tid & 7;         // 0..7

    // prologue: stage 0 K/V
    #pragma unroll
    for (int i = 0; i < 2; i++)
        CP_ASYNC16(sbase + (KS_OFF + rr[i]*68 + cc4[i]) * 4, Kb + rr[i]*64 + cc4[i]);
    CP_ASYNC16(sbase + (VS_OFF + vdk*36 + vch*4) * 4, Vb + (size_t)vdk * SS + vch * 8);
    CP_COMMIT();

    // Q fragments -> registers (loop-invariant, warp-private). Values are
    // already tf32-RNA pre-rounded by the projection; f2t is an identity.
    unsigned qf[8][4];
    {
        const float* q0 = Qb + (wr + g) * 64;       // row for frag .x/.z
        const float* q1 = Qb + (wr + g + 8) * 64;   // row for frag .y/.w
        #pragma unroll
        for (int d = 0; d < 8; d++) {
            const int k8 = d * 8;
            qf[d][0] = f2t(__ldg(q0 + k8 + c));
            qf[d][1] = f2t(__ldg(q1 + k8 + c));
            qf[d][2] = f2t(__ldg(q0 + k8 + c + 4));
            qf[d][3] = f2t(__ldg(q1 + k8 + c + 4));
        }
    }

    CP_WAIT0();
    __syncthreads();

    float O[8][4] = {};
    float m0r = -1e30f, m1r = -1e30f, l0 = 0.f, l1 = 0.f;

    for (int kt = 0; kt < 32; kt++) {
        const int s = kt & 1;
        const unsigned (*Ksc)[68] = (const unsigned(*)[68])(sh + KS_OFF + s * 4352);
        const unsigned* Vsc = sh + VS_OFF + s * 2304;   // [dk][36 words]

        if (kt < 31) {
            const int s1 = s ^ 1;
            const float* Kn = Kb + (size_t)(kt + 1) * 64 * 64;
            const __nv_bfloat16* Vn = Vb + (kt + 1) * 64;
            #pragma unroll
            for (int i = 0; i < 2; i++)
                CP_ASYNC16(sbase + (KS_OFF + s1*4352 + rr[i]*68 + cc4[i]) * 4, Kn + rr[i]*64 + cc4[i]);
            CP_ASYNC16(sbase + (VS_OFF + s1*2304 + vdk*36 + vch*4) * 4, Vn + (size_t)vdk * SS + vch * 8);
            CP_COMMIT();
        }

        // S = Q K^T (tf32; Q fragments from registers)
        float sc[8][4] = {};
        #pragma unroll
        for (int d = 0; d < 8; d++) {
            const int k8 = d * 8;
            #pragma unroll
            for (int ni = 0; ni < 8; ni++) {
                const unsigned b0 = Ksc[ni * 8 + g][k8 + c];
                const unsigned b1 = Ksc[ni * 8 + g][k8 + c + 4];
                mma8(sc[ni], qf[d][0], qf[d][1], qf[d][2], qf[d][3], b0, b1);
            }
        }

        // Online softmax (base-2)
        {
            float mx = -1e30f;
            #pragma unroll
            for (int ni = 0; ni < 8; ni++) mx = fmaxf(mx, fmaxf(sc[ni][0], sc[ni][1]));
            mx = fmaxf(mx, __shfl_xor_sync(0xffffffffu, mx, 1));
            mx = fmaxf(mx, __shfl_xor_sync(0xffffffffu, mx, 2));
            const float mn = fmaxf(m0r, mx);
            const float corr = exp2f(m0r - mn);
            m0r = mn;
            float s_ = 0.f;
            #pragma unroll
            for (int ni = 0; ni < 8; ni++) {
                sc[ni][0] = exp2f(sc[ni][0] - mn);
                sc[ni][1] = exp2f(sc[ni][1] - mn);
                s_ += sc[ni][0] + sc[ni][1];
            }
            s_ += __shfl_xor_sync(0xffffffffu, s_, 1);
            s_ += __shfl_xor_sync(0xffffffffu, s_, 2);
            l0 = l0 * corr + s_;
            #pragma unroll
            for (int ni = 0; ni < 8; ni++) { O[ni][0] *= corr; O[ni][1] *= corr; }
        }
        {
            float mx = -1e30f;
            #pragma unroll
            for (int ni = 0; ni < 8; ni++) mx = fmaxf(mx, fmaxf(sc[ni][2], sc[ni][3]));
            mx = fmaxf(mx, __shfl_xor_sync(0xffffffffu, mx, 1));
            mx = fmaxf(mx, __shfl_xor_sync(0xffffffffu, mx, 2));
            const float mn = fmaxf(m1r, mx);
            const float corr = exp2f(m1r - mn);
            m1r = mn;
            float s_ = 0.f;
            #pragma unroll
            for (int ni = 0; ni < 8; ni++) {
                sc[ni][2] = exp2f(sc[ni][2] - mn);
                sc[ni][3] = exp2f(sc[ni][3] - mn);
                s_ += sc[ni][2] + sc[ni][3];
            }
            s_ += __shfl_xor_sync(0xffffffffu, s_, 1);
            s_ += __shfl_xor_sync(0xffffffffu, s_, 2);
            l1 = l1 * corr + s_;
            #pragma unroll
            for (int ni = 0; ni < 8; ni++) { O[ni][2] *= corr; O[ni][3] *= corr; }
        }

        // O += P @ V  (bf16 k16 mma; P packed straight from score registers)
        #pragma unroll
        for (int kb = 0; kb < 4; kb++) {
            const unsigned pa0 = packbf(sc[2*kb][0],   sc[2*kb][1]);
            const unsigned pa1 = packbf(sc[2*kb][2],   sc[2*kb][3]);
            const unsigned pa2 = packbf(sc[2*kb+1][0], sc[2*kb+1][1]);
            const unsigned pa3 = packbf(sc[2*kb+1][2], sc[2*kb+1][3]);
            #pragma unroll
            for (int ni = 0; ni < 8; ni++) {
                const unsigned b0 = Vsc[(ni * 8 + g) * 36 + 8 * kb + c];
                const unsigned b1 = Vsc[(ni * 8 + g) * 36 + 8 * kb + 4 + c];
                mma16(O[ni], pa0, pa1, pa2, pa3, b0, b1);
            }
        }

        CP_WAIT0();
        __syncthreads();
    }

    // Normalize + write [B,S,D]
    const int b_ = bh >> 3, h_ = bh & 7;
    const float inv0 = 1.0f / l0, inv1 = 1.0f / l1;
    const int s0 = qt * 256 + wr + g;
    float* o0 = Out + ((size_t)(b_ * SS + s0)) * DD + h_ * 64;
    float* o1 = o0 + 8 * DD;
    #pragma unroll
    for (int ni = 0; ni < 8; ni++) {
        const int cc = ni * 8 + c * 2;
        o0[cc]     = O[ni][0] * inv0;
        o0[cc + 1] = O[ni][1] * inv0;
        o1[cc]     = O[ni][2] * inv1;
        o1[cc + 1] = O[ni][3] * inv1;
    }
}

// ---------------------------------------------------------------------------

extern "C" void kernel_launch(void* const* d_in, const int* in_sizes, int n_in,
                              void* d_out, int out_size) {
    const float* x  = (const float*)d_in[0];
    const float* Wq = (const float*)d_in[1];
    const float* bq = (const float*)d_in[2];
    const float* Wk = (const float*)d_in[3];
    const float* bk = (const float*)d_in[4];
    const float* Wv = (const float*)d_in[5];
    const float* bv = (const float*)d_in[6];
    const float* Wo = (const float*)d_in[7];
    const float* bo = (const float*)d_in[8];
    float* out = (float*)d_out;

    float *Q, *K, *attn;
    __nv_bfloat16* Vt;
    cudaGetSymbolAddress((void**)&Q, g_Q);
    cudaGetSymbolAddress((void**)&K, g_K);
    cudaGetSymbolAddress((void**)&Vt, g_Vt);
    cudaGetSymbolAddress((void**)&attn, g_attn);

    const int proj_smem = 2 * PSTG * 4;   // 55296 B
    const int attn_smem = 13312 * 4;      // 53248 B
    cudaFuncSetAttribute(qkv_proj_kernel, cudaFuncAttributeMaxDynamicSharedMemorySize, proj_smem);
    cudaFuncSetAttribute(out_proj_kernel, cudaFuncAttributeMaxDynamicSharedMemorySize, proj_smem);
    cudaFuncSetAttribute(attn_kernel,     cudaFuncAttributeMaxDynamicSharedMemorySize, attn_smem);

    // Fused QKV; Q gets 1/sqrt(64) * log2(e) folded in (exp2 softmax)
    const float qalpha = 0.125f * 1.4426950408889634f;
    qkv_proj_kernel<<<dim3(8, 32, 3), 256, proj_smem>>>(x, Wq, bq, Wk, bk, Wv, bv, qalpha);

    attn_kernel<<<dim3(8, 16), 512, attn_smem>>>(Q, K, Vt, attn);

    out_proj_kernel<<<dim3(8, 32), 256, proj_smem>>>(Wo, bo, out);
}

// round 17
// speedup vs baseline: 1.9269x; 1.0303x over previous
#include <cuda_runtime.h>
#include <cuda_bf16.h>
#include <math.h>

#define BB 2
#define SS 2048
#define DD 512
#define HH 8
#define DK 64
#define M_TOTAL (BB*SS)   // 4096

// Scratch (allocation-free)
__device__ float g_Q[BB*HH*SS*DK];
__device__ float g_K[BB*HH*SS*DK];
__device__ __nv_bfloat16 g_Vt[BB*HH*DK*SS];   // transposed: [bh][dk][s]
__device__ float g_attn[BB*SS*DD];

// ---------------------------------------------------------------------------
__device__ __forceinline__ unsigned f2t(float x) {
    unsigned r;
    asm("cvt.rna.tf32.f32 %0, %1;" : "=r"(r) : "f"(x));
    return r;
}

__device__ __forceinline__ unsigned packbf(float lo, float hi) {
    unsigned r;
    asm("cvt.rn.bf16x2.f32 %0, %1, %2;" : "=r"(r) : "f"(hi), "f"(lo));
    return r;
}

__device__ __forceinline__ void mma8(float* c,
                                     unsigned a0, unsigned a1, unsigned a2, unsigned a3,
                                     unsigned b0, unsigned b1) {
    asm volatile(
        "mma.sync.aligned.m16n8k8.row.col.f32.tf32.tf32.f32 "
        "{%0,%1,%2,%3}, {%4,%5,%6,%7}, {%8,%9}, {%0,%1,%2,%3};"
        : "+f"(c[0]), "+f"(c[1]), "+f"(c[2]), "+f"(c[3])
        : "r"(a0), "r"(a1), "r"(a2), "r"(a3), "r"(b0), "r"(b1));
}

__device__ __forceinline__ void mma16(float* c,
                                      unsigned a0, unsigned a1, unsigned a2, unsigned a3,
                                      unsigned b0, unsigned b1) {
    asm volatile(
        "mma.sync.aligned.m16n8k16.row.col.f32.bf16.bf16.f32 "
        "{%0,%1,%2,%3}, {%4,%5,%6,%7}, {%8,%9}, {%0,%1,%2,%3};"
        : "+f"(c[0]), "+f"(c[1]), "+f"(c[2]), "+f"(c[3])
        : "r"(a0), "r"(a1), "r"(a2), "r"(a3), "r"(b0), "r"(b1));
}

#define CP_ASYNC16(smem_u32, gptr) \
    asm volatile("cp.async.cg.shared.global [%0], [%1], 16;" :: "r"(smem_u32), "l"(gptr))
#define CP_COMMIT()  asm volatile("cp.async.commit_group;" ::: "memory")
#define CP_WAIT0()   asm volatile("cp.async.wait_group 0;" ::: "memory")

// ---------------------------------------------------------------------------
// Single-pass TF32 GEMM body, WIDE tile: CTA 128x128, BK=32, 8 warps (4m x 2n),
// warp tile 32x64. cp.async double-buffered raw-fp32 staging, f2t at
// fragment-load time. Per-output accumulation order identical to the 128x64
// version -> bit-identical results.
// Stage layout (words): A rows [0..128), W rows [128..256); stride PSTG.
// MODE 0: row-major [M,N] fp32.
// MODE 1: head-split [B,H,S,DK] fp32 + tf32-RNA pre-round.
// MODE 2: head-split TRANSPOSED [B,H,DK,S] bf16 (for attn V).
// ---------------------------------------------------------------------------
#define PSTG 9216   // words per stage: 256 rows * 36

template<int MODE>
__device__ __forceinline__
void proj_body(const float* __restrict__ A, const float* __restrict__ W,
               const float* __restrict__ bias, float* __restrict__ C,
               float alpha, int m0, int n0, unsigned* sh) {
    const int tid  = threadIdx.x;
    const int lane = tid & 31;
    const int warp = tid >> 5;
    const int g = lane >> 2, c = lane & 3;
    const int wm = warp & 3, wn = warp >> 2;   // 4 warps along M, 2 along N
    const unsigned sbase = (unsigned)__cvta_generic_to_shared(sh);

    // A: 128 rows x 8 chunks = 1024 -> 4/thread ; W: 128 rows x 8 chunks -> 4/thread
    int ar[4], ac[4];
    #pragma unroll
    for (int i = 0; i < 4; i++) {
        const int f = tid + i * 256;
        ar[i] = f >> 3; ac[i] = (f & 7) * 4;
    }

    // prologue: fill stage 0
    #pragma unroll
    for (int i = 0; i < 4; i++) {
        CP_ASYNC16(sbase + (ar[i]*36 + ac[i]) * 4,
                   A + (size_t)(m0 + ar[i]) * 512 + ac[i]);
        CP_ASYNC16(sbase + ((128 + ar[i])*36 + ac[i]) * 4,
                   W + (size_t)(n0 + ar[i]) * 512 + ac[i]);
    }
    CP_COMMIT();
    CP_WAIT0();
    __syncthreads();

    float acc[2][8][4] = {};

    for (int kt = 0; kt < 16; kt++) {
        const int s = kt & 1;
        const float* St = (const float*)(sh + s * PSTG);

        // fill next stage (overlaps compute)
        if (kt < 15) {
            const int s1 = s ^ 1;
            const int ko = (kt + 1) * 32;
            #pragma unroll
            for (int i = 0; i < 4; i++) {
                CP_ASYNC16(sbase + (s1*PSTG + ar[i]*36 + ac[i]) * 4,
                           A + (size_t)(m0 + ar[i]) * 512 + ko + ac[i]);
                CP_ASYNC16(sbase + (s1*PSTG + (128 + ar[i])*36 + ac[i]) * 4,
                           W + (size_t)(n0 + ar[i]) * 512 + ko + ac[i]);
            }
            CP_COMMIT();
        }

        #pragma unroll
        for (int d = 0; d < 4; d++) {
            const int k8 = d * 8;
            unsigned ab[2][4], bb[8][2];
            #pragma unroll
            for (int mi = 0; mi < 2; mi++) {
                const int rb = wm * 32 + mi * 16;
                ab[mi][0] = f2t(St[(rb + g) * 36 + k8 + c]);
                ab[mi][1] = f2t(St[(rb + g + 8) * 36 + k8 + c]);
                ab[mi][2] = f2t(St[(rb + g) * 36 + k8 + c + 4]);
                ab[mi][3] = f2t(St[(rb + g + 8) * 36 + k8 + c + 4]);
            }
            #pragma unroll
            for (int ni = 0; ni < 8; ni++) {
                const int cb = 128 + wn * 64 + ni * 8;
                bb[ni][0] = f2t(St[(cb + g) * 36 + k8 + c]);
                bb[ni][1] = f2t(St[(cb + g) * 36 + k8 + c + 4]);
            }
            #pragma unroll
            for (int mi = 0; mi < 2; mi++)
                #pragma unroll
                for (int ni = 0; ni < 8; ni++)
                    mma8(acc[mi][ni], ab[mi][0], ab[mi][1], ab[mi][2], ab[mi][3], bb[ni][0], bb[ni][1]);
        }

        CP_WAIT0();
        __syncthreads();
    }

    #pragma unroll
    for (int mi = 0; mi < 2; mi++) {
        const int r0 = m0 + wm * 32 + mi * 16 + g;
        #pragma unroll
        for (int ni = 0; ni < 8; ni++) {
            const int cc = n0 + wn * 64 + ni * 8 + c * 2;
            const float b0 = bias[cc], b1 = bias[cc + 1];
            float v[4];
            v[0] = (acc[mi][ni][0] + b0) * alpha;
            v[1] = (acc[mi][ni][1] + b1) * alpha;
            v[2] = (acc[mi][ni][2] + b0) * alpha;
            v[3] = (acc[mi][ni][3] + b1) * alpha;
            #pragma unroll
            for (int p = 0; p < 2; p++) {
                const int m = r0 + p * 8;
                #pragma unroll
                for (int q = 0; q < 2; q++) {
                    const int n = cc + q;
                    float val = v[p * 2 + q];
                    if (MODE == 0) {
                        C[(size_t)m * 512 + n] = val;
                    } else if (MODE == 1) {
                        val = __uint_as_float(f2t(val));   // pre-round for attn
                        const int b_ = m >> 11, s_ = m & 2047;
                        const int h_ = n >> 6, dk = n & 63;
                        C[(((size_t)(b_ * HH + h_)) * SS + s_) * DK + dk] = val;
                    } else {
                        const int b_ = m >> 11, s_ = m & 2047;
                        const int h_ = n >> 6, dk = n & 63;
                        __nv_bfloat16* Cb = (__nv_bfloat16*)C;
                        Cb[(((size_t)(b_ * HH + h_)) * DK + dk) * SS + s_] = __float2bfloat16(val);
                    }
                }
            }
        }
    }
}

// Fused Q/K/V projection: blockIdx.z selects weight/bias/output. NO min-blocks cap.
__global__ __launch_bounds__(256)
void qkv_proj_kernel(const float* __restrict__ x,
                     const float* __restrict__ Wq, const float* __restrict__ bq,
                     const float* __restrict__ Wk, const float* __restrict__ bk,
                     const float* __restrict__ Wv, const float* __restrict__ bv,
                     float qalpha) {
    extern __shared__ unsigned sh[];
    const int z = blockIdx.z;
    if (z == 0)
        proj_body<1>(x, Wq, bq, g_Q, qalpha, blockIdx.y * 128, blockIdx.x * 128, sh);
    else if (z == 1)
        proj_body<1>(x, Wk, bk, g_K, 1.0f, blockIdx.y * 128, blockIdx.x * 128, sh);
    else
        proj_body<2>(x, Wv, bv, (float*)g_Vt, 1.0f, blockIdx.y * 128, blockIdx.x * 128, sh);
}

__global__ __launch_bounds__(256)
void out_proj_kernel(const float* __restrict__ Wo, const float* __restrict__ bo,
                     float* __restrict__ out) {
    extern __shared__ unsigned sh[];
    proj_body<0>(g_attn, Wo, bo, out, 1.0f, blockIdx.y * 128, blockIdx.x * 128, sh);
}

// ---------------------------------------------------------------------------
// Flash attention: unchanged from R15 (verified 181.8 total). 512 threads,
// 256-row q-tile, 16 warps; Q fragments in registers; QK^T tf32; P·V bf16
// with register-packed P and pre-transposed V.
// smem (words): Ks[2][64][68] @0 | Vt[2][64][36] @8704 -> 13312 words = 53248 B
// ---------------------------------------------------------------------------
#define KS_OFF 0
#define VS_OFF 8704

__global__ __launch_bounds__(512)
void attn_kernel(const float* __restrict__ Q, const float* __restrict__ K,
                 const __nv_bfloat16* __restrict__ Vt, float* __restrict__ Out) {
    extern __shared__ unsigned sh[];

    const int tid  = threadIdx.x;
    const int lane = tid & 31;
    const int warp = tid >> 5;       // 0..15
    const int g = lane >> 2, c = lane & 3;
    const int wr = warp * 16;        // 0..240
    const int qt = blockIdx.x;       // 0..7
    const int bh = blockIdx.y;       // 0..15

    const float* Qb = Q + (size_t)bh * SS * DK + (size_t)qt * 256 * DK;
    const float* Kb = K + (size_t)bh * SS * DK;
    const __nv_bfloat16* Vb = Vt + (size_t)bh * DK * SS;   // [dk][s]

    const unsigned sbase = (unsigned)__cvta_generic_to_shared(sh);

    int rr[2], cc4[2];
    #pragma unroll
    for (int i = 0; i < 2; i++) {
        const int f = tid + i * 512;
        rr[i] = f >> 4;
        cc4[i] = (f & 15) * 4;
    }
    const int vdk = tid >> 3;        // 0..63
    const int vch = tid & 7;         // 0..7

    // prologue: stage 0 K/V
    #pragma unroll
    for (int i = 0; i < 2; i++)
        CP_ASYNC16(sbase + (KS_OFF + rr[i]*68 + cc4[i]) * 4, Kb + rr[i]*64 + cc4[i]);
    CP_ASYNC16(sbase + (VS_OFF + vdk*36 + vch*4) * 4, Vb + (size_t)vdk * SS + vch * 8);
    CP_COMMIT();

    // Q fragments -> registers (loop-invariant, warp-private; proj pre-rounded)
    unsigned qf[8][4];
    {
        const float* q0 = Qb + (wr + g) * 64;
        const float* q1 = Qb + (wr + g + 8) * 64;
        #pragma unroll
        for (int d = 0; d < 8; d++) {
            const int k8 = d * 8;
            qf[d][0] = f2t(__ldg(q0 + k8 + c));
            qf[d][1] = f2t(__ldg(q1 + k8 + c));
            qf[d][2] = f2t(__ldg(q0 + k8 + c + 4));
            qf[d][3] = f2t(__ldg(q1 + k8 + c + 4));
        }
    }

    CP_WAIT0();
    __syncthreads();

    float O[8][4] = {};
    float m0r = -1e30f, m1r = -1e30f, l0 = 0.f, l1 = 0.f;

    for (int kt = 0; kt < 32; kt++) {
        const int s = kt & 1;
        const unsigned (*Ksc)[68] = (const unsigned(*)[68])(sh + KS_OFF + s * 4352);
        const unsigned* Vsc = sh + VS_OFF + s * 2304;   // [dk][36 words]

        if (kt < 31) {
            const int s1 = s ^ 1;
            const float* Kn = Kb + (size_t)(kt + 1) * 64 * 64;
            const __nv_bfloat16* Vn = Vb + (kt + 1) * 64;
            #pragma unroll
            for (int i = 0; i < 2; i++)
                CP_ASYNC16(sbase + (KS_OFF + s1*4352 + rr[i]*68 + cc4[i]) * 4, Kn + rr[i]*64 + cc4[i]);
            CP_ASYNC16(sbase + (VS_OFF + s1*2304 + vdk*36 + vch*4) * 4, Vn + (size_t)vdk * SS + vch * 8);
            CP_COMMIT();
        }

        // S = Q K^T (tf32; Q fragments from registers)
        float sc[8][4] = {};
        #pragma unroll
        for (int d = 0; d < 8; d++) {
            const int k8 = d * 8;
            #pragma unroll
            for (int ni = 0; ni < 8; ni++) {
                const unsigned b0 = Ksc[ni * 8 + g][k8 + c];
                const unsigned b1 = Ksc[ni * 8 + g][k8 + c + 4];
                mma8(sc[ni], qf[d][0], qf[d][1], qf[d][2], qf[d][3], b0, b1);
            }
        }

        // Online softmax (base-2)
        {
            float mx = -1e30f;
            #pragma unroll
            for (int ni = 0; ni < 8; ni++) mx = fmaxf(mx, fmaxf(sc[ni][0], sc[ni][1]));
            mx = fmaxf(mx, __shfl_xor_sync(0xffffffffu, mx, 1));
            mx = fmaxf(mx, __shfl_xor_sync(0xffffffffu, mx, 2));
            const float mn = fmaxf(m0r, mx);
            const float corr = exp2f(m0r - mn);
            m0r = mn;
            float s_ = 0.f;
            #pragma unroll
            for (int ni = 0; ni < 8; ni++) {
                sc[ni][0] = exp2f(sc[ni][0] - mn);
                sc[ni][1] = exp2f(sc[ni][1] - mn);
                s_ += sc[ni][0] + sc[ni][1];
            }
            s_ += __shfl_xor_sync(0xffffffffu, s_, 1);
            s_ += __shfl_xor_sync(0xffffffffu, s_, 2);
            l0 = l0 * corr + s_;
            #pragma unroll
            for (int ni = 0; ni < 8; ni++) { O[ni][0] *= corr; O[ni][1] *= corr; }
        }
        {
            float mx = -1e30f;
            #pragma unroll
            for (int ni = 0; ni < 8; ni++) mx = fmaxf(mx, fmaxf(sc[ni][2], sc[ni][3]));
            mx = fmaxf(mx, __shfl_xor_sync(0xffffffffu, mx, 1));
            mx = fmaxf(mx, __shfl_xor_sync(0xffffffffu, mx, 2));
            const float mn = fmaxf(m1r, mx);
            const float corr = exp2f(m1r - mn);
            m1r = mn;
            float s_ = 0.f;
            #pragma unroll
            for (int ni = 0; ni < 8; ni++) {
                sc[ni][2] = exp2f(sc[ni][2] - mn);
                sc[ni][3] = exp2f(sc[ni][3] - mn);
                s_ += sc[ni][2] + sc[ni][3];
            }
            s_ += __shfl_xor_sync(0xffffffffu, s_, 1);
            s_ += __shfl_xor_sync(0xffffffffu, s_, 2);
            l1 = l1 * corr + s_;
            #pragma unroll
            for (int ni = 0; ni < 8; ni++) { O[ni][2] *= corr; O[ni][3] *= corr; }
        }

        // O += P @ V  (bf16 k16 mma; P packed straight from score registers)
        #pragma unroll
        for (int kb = 0; kb < 4; kb++) {
            const unsigned pa0 = packbf(sc[2*kb][0],   sc[2*kb][1]);
            const unsigned pa1 = packbf(sc[2*kb][2],   sc[2*kb][3]);
            const unsigned pa2 = packbf(sc[2*kb+1][0], sc[2*kb+1][1]);
            const unsigned pa3 = packbf(sc[2*kb+1][2], sc[2*kb+1][3]);
            #pragma unroll
            for (int ni = 0; ni < 8; ni++) {
                const unsigned b0 = Vsc[(ni * 8 + g) * 36 + 8 * kb + c];
                const unsigned b1 = Vsc[(ni * 8 + g) * 36 + 8 * kb + 4 + c];
                mma16(O[ni], pa0, pa1, pa2, pa3, b0, b1);
            }
        }

        CP_WAIT0();
        __syncthreads();
    }

    // Normalize + write [B,S,D]
    const int b_ = bh >> 3, h_ = bh & 7;
    const float inv0 = 1.0f / l0, inv1 = 1.0f / l1;
    const int s0 = qt * 256 + wr + g;
    float* o0 = Out + ((size_t)(b_ * SS + s0)) * DD + h_ * 64;
    float* o1 = o0 + 8 * DD;
    #pragma unroll
    for (int ni = 0; ni < 8; ni++) {
        const int cc = ni * 8 + c * 2;
        o0[cc]     = O[ni][0] * inv0;
        o0[cc + 1] = O[ni][1] * inv0;
        o1[cc]     = O[ni][2] * inv1;
        o1[cc + 1] = O[ni][3] * inv1;
    }
}

// ---------------------------------------------------------------------------

extern "C" void kernel_launch(void* const* d_in, const int* in_sizes, int n_in,
                              void* d_out, int out_size) {
    const float* x  = (const float*)d_in[0];
    const float* Wq = (const float*)d_in[1];
    const float* bq = (const float*)d_in[2];
    const float* Wk = (const float*)d_in[3];
    const float* bk = (const float*)d_in[4];
    const float* Wv = (const float*)d_in[5];
    const float* bv = (const float*)d_in[6];
    const float* Wo = (const float*)d_in[7];
    const float* bo = (const float*)d_in[8];
    float* out = (float*)d_out;

    float *Q, *K, *attn;
    __nv_bfloat16* Vt;
    cudaGetSymbolAddress((void**)&Q, g_Q);
    cudaGetSymbolAddress((void**)&K, g_K);
    cudaGetSymbolAddress((void**)&Vt, g_Vt);
    cudaGetSymbolAddress((void**)&attn, g_attn);

    const int proj_smem = 2 * PSTG * 4;   // 73728 B (2-stage, 256 rows/stage)
    const int attn_smem = 13312 * 4;      // 53248 B
    cudaFuncSetAttribute(qkv_proj_kernel, cudaFuncAttributeMaxDynamicSharedMemorySize, proj_smem);
    cudaFuncSetAttribute(out_proj_kernel, cudaFuncAttributeMaxDynamicSharedMemorySize, proj_smem);
    cudaFuncSetAttribute(attn_kernel,     cudaFuncAttributeMaxDynamicSharedMemorySize, attn_smem);

    // Fused QKV; Q gets 1/sqrt(64) * log2(e) folded in (exp2 softmax)
    const float qalpha = 0.125f * 1.4426950408889634f;
    qkv_proj_kernel<<<dim3(4, 32, 3), 256, proj_smem>>>(x, Wq, bq, Wk, bk, Wv, bv, qalpha);

    attn_kernel<<<dim3(8, 16), 512, attn_smem>>>(Q, K, Vt, attn);

    out_proj_kernel<<<dim3(4, 32), 256, proj_smem>>>(Wo, bo, out);
}